// round 1
// baseline (speedup 1.0000x reference)
#include <cuda_runtime.h>
#include <math.h>

#define EMB 1024
#define HEADS 16
#define DH 64
#define BATCH 4
#define SEQ 2048
#define MROWS (BATCH * SEQ)   // 8192

// Scratch (device globals; no runtime allocation allowed)
__device__ float g_q[(size_t)BATCH * HEADS * SEQ * DH];   // 32 MB, [B,H,S,Dh], pre-scaled by 1/8
__device__ float g_k[(size_t)BATCH * HEADS * SEQ * DH];
__device__ float g_v[(size_t)BATCH * HEADS * SEQ * DH];
__device__ float g_ctx[(size_t)MROWS * EMB];              // attention output, [B*S, EMB]

// ---------------------------------------------------------------------------
// SGEMM: C[M,N] = A[M,K] @ B[K,N] + bias, 128x128 block tile, 8x8 per thread.
// EPI==0: QKV epilogue -> scatter to g_q/g_k/g_v ([B,H,S,Dh]), q *= 0.125
// EPI==1: A is g_ctx, write C = out with bias
// ---------------------------------------------------------------------------
template <int EPI>
__global__ __launch_bounds__(256, 2) void sgemm_kernel(
    const float* __restrict__ A, const float* __restrict__ B,
    const float* __restrict__ bias, float* __restrict__ C,
    int N, int K)
{
    __shared__ float As[8][128];   // transposed A tile: As[k][m]
    __shared__ float Bs[8][128];   // natural B tile:   Bs[k][n]

    const int tid = threadIdx.x;
    const int m0 = blockIdx.y * 128;
    const int n0 = blockIdx.x * 128;
    const int mt = tid >> 4;       // 0..15 -> rows mt*8..mt*8+7
    const int nt = tid & 15;       // 0..15 -> cols nt*8..nt*8+7

    const int arow = tid >> 1;         // 0..127
    const int acol = (tid & 1) * 4;    // 0 or 4
    const int brow = tid >> 5;         // 0..7
    const int bcol = (tid & 31) * 4;   // 0..124

    const float* Ap = (EPI == 1) ? (const float*)g_ctx : A;
    const float* Ag = Ap + (size_t)(m0 + arow) * K + acol;
    const float* Bg = B + (size_t)brow * N + n0 + bcol;

    float acc[8][8];
#pragma unroll
    for (int i = 0; i < 8; i++)
#pragma unroll
        for (int j = 0; j < 8; j++) acc[i][j] = 0.f;

    for (int k0 = 0; k0 < K; k0 += 8) {
        float4 av = *(const float4*)(Ag + k0);
        float4 bv = *(const float4*)(Bg + (size_t)k0 * N);
        __syncthreads();   // previous tile fully consumed
        As[acol + 0][arow] = av.x;
        As[acol + 1][arow] = av.y;
        As[acol + 2][arow] = av.z;
        As[acol + 3][arow] = av.w;
        *(float4*)&Bs[brow][bcol] = bv;
        __syncthreads();
#pragma unroll
        for (int k = 0; k < 8; k++) {
            float4 a0 = *(const float4*)&As[k][mt * 8];
            float4 a1 = *(const float4*)&As[k][mt * 8 + 4];
            float4 b0 = *(const float4*)&Bs[k][nt * 8];
            float4 b1 = *(const float4*)&Bs[k][nt * 8 + 4];
            float a[8]  = {a0.x, a0.y, a0.z, a0.w, a1.x, a1.y, a1.z, a1.w};
            float bb[8] = {b0.x, b0.y, b0.z, b0.w, b1.x, b1.y, b1.z, b1.w};
#pragma unroll
            for (int i = 0; i < 8; i++)
#pragma unroll
                for (int j = 0; j < 8; j++)
                    acc[i][j] = fmaf(a[i], bb[j], acc[i][j]);
        }
    }

    if (EPI == 1) {
#pragma unroll
        for (int i = 0; i < 8; i++) {
            const int m = m0 + mt * 8 + i;
#pragma unroll
            for (int j = 0; j < 8; j += 4) {
                const int n = n0 + nt * 8 + j;
                float4 o;
                o.x = acc[i][j + 0] + bias[n + 0];
                o.y = acc[i][j + 1] + bias[n + 1];
                o.z = acc[i][j + 2] + bias[n + 2];
                o.w = acc[i][j + 3] + bias[n + 3];
                *(float4*)(C + (size_t)m * N + n) = o;
            }
        }
    } else {
#pragma unroll
        for (int i = 0; i < 8; i++) {
            const int m = m0 + mt * 8 + i;
            const int b = m >> 11;      // SEQ = 2048
            const int s = m & 2047;
#pragma unroll
            for (int j = 0; j < 8; j++) {
                const int n = n0 + nt * 8 + j;
                float v = acc[i][j] + bias[n];
                const int which = n >> 10;    // 0=q, 1=k, 2=v
                const int e = n & 1023;
                const int hh = e >> 6;
                const int d = e & 63;
                const size_t idx = (((size_t)(b * HEADS + hh)) * SEQ + s) * DH + d;
                if (which == 0)       g_q[idx] = v * 0.125f;  // 1/sqrt(64)
                else if (which == 1)  g_k[idx] = v;
                else                  g_v[idx] = v;
            }
        }
    }
}

// ---------------------------------------------------------------------------
// Flash attention: one CTA per (b, h, 64-row query tile). fp32, causal.
// Q, K stored transposed in smem for conflict-free float4 GEMM reads.
// Online softmax state (m, l) in registers, replicated across the 16 lanes
// that share each row, kept consistent via shfl reductions.
// ---------------------------------------------------------------------------
__global__ __launch_bounds__(256, 2) void flash_kernel()
{
    __shared__ float sQt[64][64];  // sQt[d][i]
    __shared__ float sKV[64][64];  // K phase: sKV[d][j] ; V phase: sKV[k][j]
    __shared__ float sPt[64][64];  // sPt[k][i]

    const int tid = threadIdx.x;
    const int qt = blockIdx.x;
    const int hh = blockIdx.y;
    const int bz = blockIdx.z;

    const size_t head_off = ((size_t)(bz * HEADS + hh)) * SEQ * DH;
    const float* Qg = g_q + head_off + (size_t)qt * 64 * DH;
    const float* Kg = g_k + head_off;
    const float* Vg = g_v + head_off;

    const int ty = tid >> 4;
    const int tx = tid & 15;
    const int i0 = ty * 4;   // query rows (local)
    const int j0 = tx * 4;   // key cols / head dims (local)

    const int ls = tid >> 4;        // loader: row within 16-row pass
    const int ld = (tid & 15) * 4;  // loader: d offset

    // load Q tile transposed
#pragma unroll
    for (int p = 0; p < 4; p++) {
        const int ss = ls + p * 16;
        float4 v = *(const float4*)(Qg + (size_t)ss * DH + ld);
        sQt[ld + 0][ss] = v.x;
        sQt[ld + 1][ss] = v.y;
        sQt[ld + 2][ss] = v.z;
        sQt[ld + 3][ss] = v.w;
    }

    float O[4][4];
    float mr[4], lr[4];
#pragma unroll
    for (int i = 0; i < 4; i++) {
        mr[i] = -1e30f;
        lr[i] = 0.f;
#pragma unroll
        for (int j = 0; j < 4; j++) O[i][j] = 0.f;
    }
    __syncthreads();

    for (int kt = 0; kt <= qt; kt++) {
        const float* Kt = Kg + (size_t)kt * 64 * DH;
        const float* Vt = Vg + (size_t)kt * 64 * DH;

        // K tile, transposed
#pragma unroll
        for (int p = 0; p < 4; p++) {
            const int ss = ls + p * 16;
            float4 v = *(const float4*)(Kt + (size_t)ss * DH + ld);
            sKV[ld + 0][ss] = v.x;
            sKV[ld + 1][ss] = v.y;
            sKV[ld + 2][ss] = v.z;
            sKV[ld + 3][ss] = v.w;
        }
        __syncthreads();

        // S = Q K^T (Q pre-scaled)
        float sc[4][4];
#pragma unroll
        for (int i = 0; i < 4; i++)
#pragma unroll
            for (int j = 0; j < 4; j++) sc[i][j] = 0.f;
#pragma unroll
        for (int d = 0; d < 64; d++) {
            float4 a = *(const float4*)&sQt[d][i0];
            float4 bb = *(const float4*)&sKV[d][j0];
            float av[4] = {a.x, a.y, a.z, a.w};
            float bv[4] = {bb.x, bb.y, bb.z, bb.w};
#pragma unroll
            for (int i = 0; i < 4; i++)
#pragma unroll
                for (int j = 0; j < 4; j++)
                    sc[i][j] = fmaf(av[i], bv[j], sc[i][j]);
        }
        __syncthreads();   // everyone done reading K

        // overwrite buffer with V (natural layout), no one reads until next sync
#pragma unroll
        for (int p = 0; p < 4; p++) {
            const int ss = ls + p * 16;
            *(float4*)&sKV[ss][ld] = *(const float4*)(Vt + (size_t)ss * DH + ld);
        }

        // causal mask (diagonal tile only)
        if (kt == qt) {
#pragma unroll
            for (int i = 0; i < 4; i++)
#pragma unroll
                for (int j = 0; j < 4; j++)
                    if (j0 + j > i0 + i) sc[i][j] = -1e30f;
        }

        // online softmax, state in registers (consistent across 16 lanes/row)
#pragma unroll
        for (int i = 0; i < 4; i++) {
            float rm = fmaxf(fmaxf(sc[i][0], sc[i][1]), fmaxf(sc[i][2], sc[i][3]));
#pragma unroll
            for (int o = 8; o >= 1; o >>= 1)
                rm = fmaxf(rm, __shfl_xor_sync(0xffffffffu, rm, o));
            const float mnew = fmaxf(mr[i], rm);
            const float scale = __expf(mr[i] - mnew);
            float rs = 0.f;
#pragma unroll
            for (int j = 0; j < 4; j++) {
                const float pv = __expf(sc[i][j] - mnew);
                sc[i][j] = pv;
                rs += pv;
            }
#pragma unroll
            for (int o = 8; o >= 1; o >>= 1)
                rs += __shfl_xor_sync(0xffffffffu, rs, o);
            lr[i] = lr[i] * scale + rs;
            mr[i] = mnew;
#pragma unroll
            for (int j = 0; j < 4; j++) O[i][j] *= scale;
        }

        // store P transposed
#pragma unroll
        for (int i = 0; i < 4; i++)
#pragma unroll
            for (int j = 0; j < 4; j++)
                sPt[j0 + j][i0 + i] = sc[i][j];
        __syncthreads();   // P and V visible

        // O += P V
#pragma unroll
        for (int k = 0; k < 64; k++) {
            float4 a = *(const float4*)&sPt[k][i0];
            float4 bb = *(const float4*)&sKV[k][j0];
            float av[4] = {a.x, a.y, a.z, a.w};
            float bv[4] = {bb.x, bb.y, bb.z, bb.w};
#pragma unroll
            for (int i = 0; i < 4; i++)
#pragma unroll
                for (int j = 0; j < 4; j++)
                    O[i][j] = fmaf(av[i], bv[j], O[i][j]);
        }
        __syncthreads();   // done reading P/V before next tile overwrites
    }

    // normalize + write merged-head ctx [B*S, EMB]
    float* dst = g_ctx + ((size_t)bz * SEQ + (size_t)qt * 64) * EMB + hh * DH;
#pragma unroll
    for (int i = 0; i < 4; i++) {
        const float inv = 1.f / lr[i];
        float4 o;
        o.x = O[i][0] * inv;
        o.y = O[i][1] * inv;
        o.z = O[i][2] * inv;
        o.w = O[i][3] * inv;
        *(float4*)(dst + (size_t)(i0 + i) * EMB + j0) = o;
    }
}

// ---------------------------------------------------------------------------
extern "C" void kernel_launch(void* const* d_in, const int* in_sizes, int n_in,
                              void* d_out, int out_size)
{
    const float* x     = (const float*)d_in[0];  // [4,2048,1024]
    const float* w_qkv = (const float*)d_in[1];  // [1024,3072]
    const float* b_qkv = (const float*)d_in[2];  // [3072]
    const float* w_fc  = (const float*)d_in[3];  // [1024,1024]
    const float* b_fc  = (const float*)d_in[4];  // [1024]
    float* out = (float*)d_out;                  // [4,2048,1024]

    // 1) QKV projection -> g_q/g_k/g_v
    sgemm_kernel<0><<<dim3(3 * EMB / 128, MROWS / 128), 256>>>(
        x, w_qkv, b_qkv, nullptr, 3 * EMB, EMB);

    // 2) causal flash attention -> g_ctx
    flash_kernel<<<dim3(SEQ / 64, HEADS, BATCH), 256>>>();

    // 3) output projection
    sgemm_kernel<1><<<dim3(EMB / 128, MROWS / 128), 256>>>(
        nullptr, w_fc, b_fc, out, EMB, EMB);
}

// round 3
// speedup vs baseline: 3.0143x; 3.0143x over previous
#include <cuda_runtime.h>
#include <cuda_fp16.h>
#include <math.h>
#include <stdint.h>

#define EMB 1024
#define HEADS 16
#define DH 64
#define BATCH 4
#define SEQ 2048
#define MROWS (BATCH * SEQ)   // 8192
#define K3 (3 * EMB)          // 3072: concatenated hi/lo K for projections

// ---------------- scratch (device globals; no runtime allocation) ----------
__device__ __half g_xA   [(size_t)MROWS * K3];        // [xh | xh | xl]
__device__ __half g_wqkvB[(size_t)K3 * (3 * EMB)];    // [wh ; wl ; wh]
__device__ __half g_wfcB [(size_t)K3 * EMB];          // [wh ; wl ; wh]
__device__ __half g_q    [(size_t)BATCH * HEADS * SEQ * 128];  // [qh | ql], q pre-scaled 1/8
__device__ __half g_k    [(size_t)BATCH * HEADS * SEQ * 192];  // [kh | kl | kh]
__device__ __half g_v    [(size_t)BATCH * HEADS * SEQ * 64];
__device__ __half g_ctx  [(size_t)MROWS * K3];        // [ch | ch | cl]

// ---------------- helpers --------------------------------------------------
__device__ __forceinline__ uint32_t smem_u32(const void* p) {
    return (uint32_t)__cvta_generic_to_shared(p);
}
__device__ __forceinline__ void ldm_x4(uint32_t& r0, uint32_t& r1, uint32_t& r2, uint32_t& r3, uint32_t addr) {
    asm volatile("ldmatrix.sync.aligned.m8n8.x4.shared.b16 { %0, %1, %2, %3 }, [ %4 ];"
                 : "=r"(r0), "=r"(r1), "=r"(r2), "=r"(r3) : "r"(addr));
}
__device__ __forceinline__ void ldm_x4_t(uint32_t& r0, uint32_t& r1, uint32_t& r2, uint32_t& r3, uint32_t addr) {
    asm volatile("ldmatrix.sync.aligned.m8n8.x4.trans.shared.b16 { %0, %1, %2, %3 }, [ %4 ];"
                 : "=r"(r0), "=r"(r1), "=r"(r2), "=r"(r3) : "r"(addr));
}
__device__ __forceinline__ void mma16816(float* c, uint32_t a0, uint32_t a1, uint32_t a2, uint32_t a3,
                                         uint32_t b0, uint32_t b1) {
    asm volatile("mma.sync.aligned.m16n8k16.row.col.f32.f16.f16.f32 "
                 "{ %0, %1, %2, %3 }, { %4, %5, %6, %7 }, { %8, %9 }, { %0, %1, %2, %3 };"
                 : "+f"(c[0]), "+f"(c[1]), "+f"(c[2]), "+f"(c[3])
                 : "r"(a0), "r"(a1), "r"(a2), "r"(a3), "r"(b0), "r"(b1));
}
__device__ __forceinline__ uint32_t packh2(float a, float b) {
    __half2 h = __floats2half2_rn(a, b);
    return *(uint32_t*)&h;
}

// ---------------- fp32 -> hi/lo fp16 split ---------------------------------
// SEL 0: x     [R=8192,C=1024] -> g_xA rows of width 3C: [h | h | l]
// SEL 1: w_qkv [R=1024,C=3072] -> g_wqkvB: row blocks [h ; l ; h]
// SEL 2: w_fc  [R=1024,C=1024] -> g_wfcB:  row blocks [h ; l ; h]
template <int SEL>
__global__ void split_kernel(const float* __restrict__ src, int R, int C) {
    __half* dst = (SEL == 0) ? g_xA : (SEL == 1) ? g_wqkvB : g_wfcB;
    size_t i = ((size_t)blockIdx.x * blockDim.x + threadIdx.x) * 2;
    if (i >= (size_t)R * C) return;
    float2 v = *(const float2*)(src + i);
    __half h0 = __float2half_rn(v.x);
    __half h1 = __float2half_rn(v.y);
    __half l0 = __float2half_rn(v.x - __half2float(h0));
    __half l1 = __float2half_rn(v.y - __half2float(h1));
    __half2 hv = __halves2half2(h0, h1);
    __half2 lv = __halves2half2(l0, l1);
    if (SEL == 0) {
        int r = (int)(i / C), c = (int)(i % C);
        size_t base = (size_t)r * (3 * C) + c;
        *(__half2*)(dst + base)         = hv;
        *(__half2*)(dst + base + C)     = hv;
        *(__half2*)(dst + base + 2 * C) = lv;
    } else {
        size_t RC = (size_t)R * C;
        *(__half2*)(dst + i)            = hv;
        *(__half2*)(dst + i + RC)       = lv;
        *(__half2*)(dst + i + 2 * RC)   = hv;
    }
}

// ---------------- HGEMM: 128x128 tile, K=3072, 8 warps, mma.m16n8k16 ------
// EPI 0: A=g_xA, B=g_wqkvB (N=3072); scatter hi/lo to g_q/g_k/g_v
// EPI 1: A=g_ctx, B=g_wfcB (N=1024); write fp32 out + bias
template <int EPI>
__global__ __launch_bounds__(256) void hgemm_kernel(
    const float* __restrict__ bias, float* __restrict__ C, int N)
{
    __shared__ __half sA[128][40];
    __shared__ __half sB[32][136];

    const __half* __restrict__ A = (EPI == 0) ? g_xA : g_ctx;
    const __half* __restrict__ B = (EPI == 0) ? g_wqkvB : g_wfcB;

    const int tid = threadIdx.x;
    const int wid = tid >> 5, lane = tid & 31;
    const int wm = (wid >> 2) * 64;
    const int wn = (wid & 3) * 32;
    const int m0 = blockIdx.y * 128;
    const int n0 = blockIdx.x * 128;

    float acc[4][4][4];
#pragma unroll
    for (int mt = 0; mt < 4; mt++)
#pragma unroll
        for (int nt = 0; nt < 4; nt++)
#pragma unroll
            for (int r = 0; r < 4; r++) acc[mt][nt][r] = 0.f;

    const int ar0 = tid >> 2, ac0 = (tid & 3) * 8;
    const int br0 = tid >> 4, bc0 = (tid & 15) * 8;

    for (int k0 = 0; k0 < K3; k0 += 32) {
        uint4 av0 = *(const uint4*)(A + (size_t)(m0 + ar0) * K3 + k0 + ac0);
        uint4 av1 = *(const uint4*)(A + (size_t)(m0 + ar0 + 64) * K3 + k0 + ac0);
        uint4 bv0 = *(const uint4*)(B + (size_t)(k0 + br0) * N + n0 + bc0);
        uint4 bv1 = *(const uint4*)(B + (size_t)(k0 + br0 + 16) * N + n0 + bc0);
        __syncthreads();
        *(uint4*)&sA[ar0][ac0]      = av0;
        *(uint4*)&sA[ar0 + 64][ac0] = av1;
        *(uint4*)&sB[br0][bc0]      = bv0;
        *(uint4*)&sB[br0 + 16][bc0] = bv1;
        __syncthreads();

#pragma unroll
        for (int ks = 0; ks < 2; ks++) {
            uint32_t a[4][4];
#pragma unroll
            for (int mt = 0; mt < 4; mt++)
                ldm_x4(a[mt][0], a[mt][1], a[mt][2], a[mt][3],
                       smem_u32(&sA[wm + mt * 16 + (lane & 15)][ks * 16 + (lane >> 4) * 8]));
            uint32_t b[8];
#pragma unroll
            for (int nn = 0; nn < 2; nn++)
                ldm_x4_t(b[nn * 4 + 0], b[nn * 4 + 1], b[nn * 4 + 2], b[nn * 4 + 3],
                         smem_u32(&sB[ks * 16 + (lane & 15)][wn + nn * 16 + (lane >> 4) * 8]));
#pragma unroll
            for (int mt = 0; mt < 4; mt++)
#pragma unroll
                for (int nt = 0; nt < 4; nt++)
                    mma16816(acc[mt][nt], a[mt][0], a[mt][1], a[mt][2], a[mt][3],
                             b[nt * 2], b[nt * 2 + 1]);
        }
    }

#pragma unroll
    for (int mt = 0; mt < 4; mt++) {
#pragma unroll
        for (int nt = 0; nt < 4; nt++) {
#pragma unroll
            for (int ri = 0; ri < 2; ri++) {
                const int m = m0 + wm + mt * 16 + (lane >> 2) + ri * 8;
                const int n = n0 + wn + nt * 8 + 2 * (lane & 3);
                float f0 = acc[mt][nt][ri * 2 + 0] + bias[n];
                float f1 = acc[mt][nt][ri * 2 + 1] + bias[n + 1];
                if (EPI == 1) {
                    float2 o;
                    o.x = f0;
                    o.y = f1;
                    *(float2*)(C + (size_t)m * N + n) = o;
                } else {
                    const int bb = m >> 11;
                    const int s  = m & 2047;
                    const int wh = n >> 10;
                    const int e  = n & 1023;
                    const int hd = e >> 6;
                    const int d  = e & 63;
                    if (wh == 0) { f0 *= 0.125f; f1 *= 0.125f; }
                    __half h0 = __float2half_rn(f0);
                    __half h1 = __float2half_rn(f1);
                    __half l0 = __float2half_rn(f0 - __half2float(h0));
                    __half l1 = __float2half_rn(f1 - __half2float(h1));
                    __half2 hv = __halves2half2(h0, h1);
                    __half2 lv = __halves2half2(l0, l1);
                    const size_t rowb = ((size_t)(bb * HEADS + hd)) * SEQ + s;
                    if (wh == 0) {
                        __half* p = g_q + rowb * 128 + d;
                        *(__half2*)p        = hv;
                        *(__half2*)(p + 64) = lv;
                    } else if (wh == 1) {
                        __half* p = g_k + rowb * 192 + d;
                        *(__half2*)p         = hv;
                        *(__half2*)(p + 64)  = lv;
                        *(__half2*)(p + 128) = hv;
                    } else {
                        *(__half2*)(g_v + rowb * 64 + d) = hv;
                    }
                }
            }
        }
    }
}

// ---------------- flash attention: split-precision scores, 4 warps --------
#define FLASH_SMEM (64 * 136 * 2 + 64 * 200 * 2 + 64 * 72 * 2)  // 52224 B

__global__ __launch_bounds__(128) void flash_kernel()
{
    extern __shared__ __half fsm[];
    __half (*sQ)[136] = (__half (*)[136])fsm;                       // [row][qh|ql] 128+pad
    __half (*sK)[200] = (__half (*)[200])(fsm + 64 * 136);          // [row][kh|kl|kh] 192+pad
    __half (*sV)[72]  = (__half (*)[72])(fsm + 64 * 136 + 64 * 200);

    const int tid = threadIdx.x, wid = tid >> 5, lane = tid & 31;
    const int qt = blockIdx.x, hh = blockIdx.y, bz = blockIdx.z;

    const size_t hrow = ((size_t)(bz * HEADS + hh)) * SEQ;
    const __half* Qg = g_q + (hrow + (size_t)qt * 64) * 128;
    const __half* Kg = g_k + hrow * 192;
    const __half* Vg = g_v + hrow * 64;

    // load Q tile (64 x 128)
#pragma unroll
    for (int i = 0; i < 8; i++) {
        int u = tid + i * 128;
        int row = u >> 4, c = (u & 15) * 8;
        *(uint4*)&sQ[row][c] = *(const uint4*)(Qg + (size_t)row * 128 + c);
    }
    __syncthreads();

    // hoist Q fragments: qf[0..3]=qh (d 0..63), qf[4..7]=ql (d 64..127)
    uint32_t qf[8][4];
#pragma unroll
    for (int ks = 0; ks < 8; ks++)
        ldm_x4(qf[ks][0], qf[ks][1], qf[ks][2], qf[ks][3],
               smem_u32(&sQ[wid * 16 + (lane & 15)][ks * 16 + (lane >> 4) * 8]));

    float O[8][4];
#pragma unroll
    for (int dt = 0; dt < 8; dt++)
#pragma unroll
        for (int r = 0; r < 4; r++) O[dt][r] = 0.f;
    float mrow[2];
    float lrow[2];
    mrow[0] = -1e30f; mrow[1] = -1e30f;
    lrow[0] = 0.f;    lrow[1] = 0.f;

    const int qrow0 = wid * 16 + (lane >> 2);

    for (int kt = 0; kt <= qt; kt++) {
        __syncthreads();
        const __half* Kt = Kg + (size_t)kt * 64 * 192;
        const __half* Vt = Vg + (size_t)kt * 64 * 64;
#pragma unroll
        for (int i = 0; i < 12; i++) {           // K tile 64 x 192
            int u = tid + i * 128;
            int row = u / 24, c = (u % 24) * 8;
            *(uint4*)&sK[row][c] = *(const uint4*)(Kt + (size_t)row * 192 + c);
        }
#pragma unroll
        for (int i = 0; i < 4; i++) {            // V tile 64 x 64
            int u = tid + i * 128;
            int row = u >> 3, c = (u & 7) * 8;
            *(uint4*)&sV[row][c] = *(const uint4*)(Vt + (size_t)row * 64 + c);
        }
        __syncthreads();

        // ---- S = qh kh + qh kl + ql kh : 12 k16 steps over sK's 192 cols --
        float S[8][4];
#pragma unroll
        for (int nt = 0; nt < 8; nt++)
#pragma unroll
            for (int r = 0; r < 4; r++) S[nt][r] = 0.f;

        const int krow = (lane >> 4) * 8 + (lane & 7);
        const int kcol = ((lane >> 3) & 1) * 8;
#pragma unroll
        for (int ks = 0; ks < 12; ks++) {
            const int qi = (ks < 4) ? ks : (ks - 4);   // 0-3:qh, 4-7:qh, 8-11:ql
#pragma unroll
            for (int jp = 0; jp < 4; jp++) {
                uint32_t b0, b1, b2, b3;
                ldm_x4(b0, b1, b2, b3,
                       smem_u32(&sK[jp * 16 + krow][ks * 16 + kcol]));
                mma16816(S[jp * 2 + 0], qf[qi][0], qf[qi][1], qf[qi][2], qf[qi][3], b0, b1);
                mma16816(S[jp * 2 + 1], qf[qi][0], qf[qi][1], qf[qi][2], qf[qi][3], b2, b3);
            }
        }

        // ---- causal mask on diagonal tile ----
        if (kt == qt) {
#pragma unroll
            for (int nt = 0; nt < 8; nt++) {
                const int jc = nt * 8 + 2 * (lane & 3);
#pragma unroll
                for (int ri = 0; ri < 2; ri++) {
                    const int ii = qrow0 + ri * 8;
                    if (jc     > ii) S[nt][ri * 2 + 0] = -1e30f;
                    if (jc + 1 > ii) S[nt][ri * 2 + 1] = -1e30f;
                }
            }
        }

        // ---- online softmax ----
#pragma unroll
        for (int ri = 0; ri < 2; ri++) {
            float tmax = -1e30f;
#pragma unroll
            for (int nt = 0; nt < 8; nt++)
                tmax = fmaxf(tmax, fmaxf(S[nt][ri * 2], S[nt][ri * 2 + 1]));
            tmax = fmaxf(tmax, __shfl_xor_sync(0xffffffffu, tmax, 1));
            tmax = fmaxf(tmax, __shfl_xor_sync(0xffffffffu, tmax, 2));
            const float mnew = fmaxf(mrow[ri], tmax);
            const float scale = __expf(mrow[ri] - mnew);
            float rs = 0.f;
#pragma unroll
            for (int nt = 0; nt < 8; nt++) {
                float p0 = __expf(S[nt][ri * 2 + 0] - mnew);
                float p1 = __expf(S[nt][ri * 2 + 1] - mnew);
                S[nt][ri * 2 + 0] = p0;
                S[nt][ri * 2 + 1] = p1;
                rs += p0 + p1;
            }
            rs += __shfl_xor_sync(0xffffffffu, rs, 1);
            rs += __shfl_xor_sync(0xffffffffu, rs, 2);
            lrow[ri] = lrow[ri] * scale + rs;
            mrow[ri] = mnew;
#pragma unroll
            for (int dt = 0; dt < 8; dt++) {
                O[dt][ri * 2 + 0] *= scale;
                O[dt][ri * 2 + 1] *= scale;
            }
        }

        // ---- O += P V ----
        const int vrow = lane & 15;
        const int vcol = (lane >> 4) * 8;
#pragma unroll
        for (int kk = 0; kk < 4; kk++) {
            uint32_t a0 = packh2(S[kk * 2 + 0][0], S[kk * 2 + 0][1]);
            uint32_t a1 = packh2(S[kk * 2 + 0][2], S[kk * 2 + 0][3]);
            uint32_t a2 = packh2(S[kk * 2 + 1][0], S[kk * 2 + 1][1]);
            uint32_t a3 = packh2(S[kk * 2 + 1][2], S[kk * 2 + 1][3]);
#pragma unroll
            for (int dp = 0; dp < 4; dp++) {
                uint32_t b0, b1, b2, b3;
                ldm_x4_t(b0, b1, b2, b3,
                         smem_u32(&sV[kk * 16 + vrow][dp * 16 + vcol]));
                mma16816(O[dp * 2 + 0], a0, a1, a2, a3, b0, b1);
                mma16816(O[dp * 2 + 1], a0, a1, a2, a3, b2, b3);
            }
        }
    }

    // ---- normalize + write ctx split [ch | ch | cl], row width 3072 ----
#pragma unroll
    for (int ri = 0; ri < 2; ri++) {
        const float inv = 1.f / lrow[ri];
        const size_t mg = (size_t)bz * SEQ + (size_t)qt * 64 + qrow0 + ri * 8;
#pragma unroll
        for (int dt = 0; dt < 8; dt++) {
            const int col = hh * 64 + dt * 8 + 2 * (lane & 3);
            float f0 = O[dt][ri * 2 + 0] * inv;
            float f1 = O[dt][ri * 2 + 1] * inv;
            __half h0 = __float2half_rn(f0);
            __half h1 = __float2half_rn(f1);
            __half l0 = __float2half_rn(f0 - __half2float(h0));
            __half l1 = __float2half_rn(f1 - __half2float(h1));
            __half2 hv = __halves2half2(h0, h1);
            __half2 lv = __halves2half2(l0, l1);
            __half* p = g_ctx + mg * K3 + col;
            *(__half2*)(p)        = hv;
            *(__half2*)(p + 1024) = hv;
            *(__half2*)(p + 2048) = lv;
        }
    }
}

// ---------------------------------------------------------------------------
extern "C" void kernel_launch(void* const* d_in, const int* in_sizes, int n_in,
                              void* d_out, int out_size)
{
    const float* x     = (const float*)d_in[0];
    const float* w_qkv = (const float*)d_in[1];
    const float* b_qkv = (const float*)d_in[2];
    const float* w_fc  = (const float*)d_in[3];
    const float* b_fc  = (const float*)d_in[4];
    float* out = (float*)d_out;

    split_kernel<0><<<MROWS * EMB / 2 / 256, 256>>>(x, MROWS, EMB);
    split_kernel<1><<<EMB * 3 * EMB / 2 / 256, 256>>>(w_qkv, EMB, 3 * EMB);
    split_kernel<2><<<EMB * EMB / 2 / 256, 256>>>(w_fc, EMB, EMB);

    // 1) QKV projection (split-precision fp16 tensor cores)
    hgemm_kernel<0><<<dim3(24, 64), 256>>>(b_qkv, nullptr, 3 * EMB);

    // 2) causal flash attention (split-precision scores)
    cudaFuncSetAttribute(flash_kernel, cudaFuncAttributeMaxDynamicSharedMemorySize, FLASH_SMEM);
    flash_kernel<<<dim3(SEQ / 64, HEADS, BATCH), 128, FLASH_SMEM>>>();

    // 3) output projection
    hgemm_kernel<1><<<dim3(8, 64), 256>>>(b_fc, out, EMB);
}

// round 4
// speedup vs baseline: 3.2174x; 1.0674x over previous
#include <cuda_runtime.h>
#include <cuda_fp16.h>
#include <math.h>
#include <stdint.h>

#define EMB 1024
#define HEADS 16
#define DH 64
#define BATCH 4
#define SEQ 2048
#define MROWS (BATCH * SEQ)   // 8192
#define K3 (3 * EMB)          // 3072: concatenated hi/lo K for projections

// ---------------- scratch (device globals; no runtime allocation) ----------
__device__ __half g_xA   [(size_t)MROWS * K3];        // [xh | xh | xl]
__device__ __half g_wqkvB[(size_t)K3 * (3 * EMB)];    // [wh ; wl ; wh]
__device__ __half g_wfcB [(size_t)K3 * EMB];          // [wh ; wl ; wh]
__device__ __half g_q    [(size_t)BATCH * HEADS * SEQ * 128];  // [qh | ql], q pre-scaled 1/8
__device__ __half g_k    [(size_t)BATCH * HEADS * SEQ * 192];  // [kh | kl | kh]
__device__ __half g_v    [(size_t)BATCH * HEADS * SEQ * 64];
__device__ __half g_ctx  [(size_t)MROWS * K3];        // [ch | ch | cl]

// ---------------- helpers --------------------------------------------------
__device__ __forceinline__ uint32_t smem_u32(const void* p) {
    return (uint32_t)__cvta_generic_to_shared(p);
}
__device__ __forceinline__ void ldm_x4(uint32_t& r0, uint32_t& r1, uint32_t& r2, uint32_t& r3, uint32_t addr) {
    asm volatile("ldmatrix.sync.aligned.m8n8.x4.shared.b16 { %0, %1, %2, %3 }, [ %4 ];"
                 : "=r"(r0), "=r"(r1), "=r"(r2), "=r"(r3) : "r"(addr));
}
__device__ __forceinline__ void ldm_x4_t(uint32_t& r0, uint32_t& r1, uint32_t& r2, uint32_t& r3, uint32_t addr) {
    asm volatile("ldmatrix.sync.aligned.m8n8.x4.trans.shared.b16 { %0, %1, %2, %3 }, [ %4 ];"
                 : "=r"(r0), "=r"(r1), "=r"(r2), "=r"(r3) : "r"(addr));
}
__device__ __forceinline__ void mma16816(float* c, uint32_t a0, uint32_t a1, uint32_t a2, uint32_t a3,
                                         uint32_t b0, uint32_t b1) {
    asm volatile("mma.sync.aligned.m16n8k16.row.col.f32.f16.f16.f32 "
                 "{ %0, %1, %2, %3 }, { %4, %5, %6, %7 }, { %8, %9 }, { %0, %1, %2, %3 };"
                 : "+f"(c[0]), "+f"(c[1]), "+f"(c[2]), "+f"(c[3])
                 : "r"(a0), "r"(a1), "r"(a2), "r"(a3), "r"(b0), "r"(b1));
}
__device__ __forceinline__ uint32_t packh2(float a, float b) {
    __half2 h = __floats2half2_rn(a, b);
    return *(uint32_t*)&h;
}
__device__ __forceinline__ void cpa16(void* s, const void* g) {
    asm volatile("cp.async.cg.shared.global [ %0 ], [ %1 ], 16;"
                 :: "r"(smem_u32(s)), "l"(g));
}
__device__ __forceinline__ void cp_commit() {
    asm volatile("cp.async.commit_group;");
}
template <int N>
__device__ __forceinline__ void cp_wait() {
    asm volatile("cp.async.wait_group %0;" :: "n"(N));
}

// ---------------- fp32 -> hi/lo fp16 split ---------------------------------
template <int SEL>
__global__ void split_kernel(const float* __restrict__ src, int R, int C) {
    __half* dst = (SEL == 0) ? g_xA : (SEL == 1) ? g_wqkvB : g_wfcB;
    size_t i = ((size_t)blockIdx.x * blockDim.x + threadIdx.x) * 2;
    if (i >= (size_t)R * C) return;
    float2 v = *(const float2*)(src + i);
    __half h0 = __float2half_rn(v.x);
    __half h1 = __float2half_rn(v.y);
    __half l0 = __float2half_rn(v.x - __half2float(h0));
    __half l1 = __float2half_rn(v.y - __half2float(h1));
    __half2 hv = __halves2half2(h0, h1);
    __half2 lv = __halves2half2(l0, l1);
    if (SEL == 0) {
        int r = (int)(i / C), c = (int)(i % C);
        size_t base = (size_t)r * (3 * C) + c;
        *(__half2*)(dst + base)         = hv;
        *(__half2*)(dst + base + C)     = hv;
        *(__half2*)(dst + base + 2 * C) = lv;
    } else {
        size_t RC = (size_t)R * C;
        *(__half2*)(dst + i)            = hv;
        *(__half2*)(dst + i + RC)       = lv;
        *(__half2*)(dst + i + 2 * RC)   = hv;
    }
}

// ---------------- HGEMM: 128x128 tile, K=3072, 3-stage cp.async ------------
#define GSTG 3
#define SA_STRIDE (128 * 40)
#define SB_STRIDE (32 * 136)
#define HGEMM_SMEM ((GSTG * (SA_STRIDE + SB_STRIDE)) * 2)   // 56832 B

template <int EPI>
__global__ __launch_bounds__(256, 2) void hgemm_kernel(
    const float* __restrict__ bias, float* __restrict__ C, int N)
{
    extern __shared__ __half hsm[];
    // sA[stage]: 128 x 40, sB[stage]: 32 x 136
    __half* sAbase = hsm;
    __half* sBbase = hsm + GSTG * SA_STRIDE;

    const __half* __restrict__ A = (EPI == 0) ? g_xA : g_ctx;
    const __half* __restrict__ B = (EPI == 0) ? g_wqkvB : g_wfcB;

    const int tid = threadIdx.x;
    const int wid = tid >> 5, lane = tid & 31;
    const int wm = (wid >> 2) * 64;
    const int wn = (wid & 3) * 32;
    const int m0 = blockIdx.y * 128;
    const int n0 = blockIdx.x * 128;

    float acc[4][4][4];
#pragma unroll
    for (int mt = 0; mt < 4; mt++)
#pragma unroll
        for (int nt = 0; nt < 4; nt++)
#pragma unroll
            for (int r = 0; r < 4; r++) acc[mt][nt][r] = 0.f;

    const int ar0 = tid >> 2, ac0 = (tid & 3) * 8;
    const int br0 = tid >> 4, bc0 = (tid & 15) * 8;

    const __half* Ag0 = A + (size_t)(m0 + ar0) * K3 + ac0;
    const __half* Ag1 = A + (size_t)(m0 + ar0 + 64) * K3 + ac0;
    const __half* Bg0 = B + (size_t)br0 * N + n0 + bc0;
    const __half* Bg1 = B + (size_t)(br0 + 16) * N + n0 + bc0;

#define LOAD_TILE(t, stg) do {                                             \
        const int k0_ = (t) * 32;                                         \
        __half* sA_ = sAbase + (stg) * SA_STRIDE;                         \
        __half* sB_ = sBbase + (stg) * SB_STRIDE;                         \
        cpa16(sA_ + ar0 * 40 + ac0,        Ag0 + k0_);                    \
        cpa16(sA_ + (ar0 + 64) * 40 + ac0, Ag1 + k0_);                    \
        cpa16(sB_ + br0 * 136 + bc0,       Bg0 + (size_t)k0_ * N);        \
        cpa16(sB_ + (br0 + 16) * 136 + bc0, Bg1 + (size_t)k0_ * N);       \
        cp_commit();                                                      \
    } while (0)

    const int T = K3 / 32;    // 96
    LOAD_TILE(0, 0);
    LOAD_TILE(1, 1);

    int stg = 0;
    for (int t = 0; t < T; t++) {
        if (t < T - 1) cp_wait<1>(); else cp_wait<0>();
        __syncthreads();
        if (t + 2 < T) {
            int ns = stg + 2; if (ns >= GSTG) ns -= GSTG;
            LOAD_TILE(t + 2, ns);
        }
        __half* sA_ = sAbase + stg * SA_STRIDE;
        __half* sB_ = sBbase + stg * SB_STRIDE;
#pragma unroll
        for (int ks = 0; ks < 2; ks++) {
            uint32_t a[4][4];
#pragma unroll
            for (int mt = 0; mt < 4; mt++)
                ldm_x4(a[mt][0], a[mt][1], a[mt][2], a[mt][3],
                       smem_u32(sA_ + (wm + mt * 16 + (lane & 15)) * 40 + ks * 16 + (lane >> 4) * 8));
            uint32_t b[8];
#pragma unroll
            for (int nn = 0; nn < 2; nn++)
                ldm_x4_t(b[nn * 4 + 0], b[nn * 4 + 1], b[nn * 4 + 2], b[nn * 4 + 3],
                         smem_u32(sB_ + (ks * 16 + (lane & 15)) * 136 + wn + nn * 16 + (lane >> 4) * 8));
#pragma unroll
            for (int mt = 0; mt < 4; mt++)
#pragma unroll
                for (int nt = 0; nt < 4; nt++)
                    mma16816(acc[mt][nt], a[mt][0], a[mt][1], a[mt][2], a[mt][3],
                             b[nt * 2], b[nt * 2 + 1]);
        }
        stg++; if (stg >= GSTG) stg = 0;
    }
#undef LOAD_TILE

#pragma unroll
    for (int mt = 0; mt < 4; mt++) {
#pragma unroll
        for (int nt = 0; nt < 4; nt++) {
#pragma unroll
            for (int ri = 0; ri < 2; ri++) {
                const int m = m0 + wm + mt * 16 + (lane >> 2) + ri * 8;
                const int n = n0 + wn + nt * 8 + 2 * (lane & 3);
                float f0 = acc[mt][nt][ri * 2 + 0] + bias[n];
                float f1 = acc[mt][nt][ri * 2 + 1] + bias[n + 1];
                if (EPI == 1) {
                    float2 o;
                    o.x = f0;
                    o.y = f1;
                    *(float2*)(C + (size_t)m * N + n) = o;
                } else {
                    const int bb = m >> 11;
                    const int s  = m & 2047;
                    const int wh = n >> 10;
                    const int e  = n & 1023;
                    const int hd = e >> 6;
                    const int d  = e & 63;
                    if (wh == 0) { f0 *= 0.125f; f1 *= 0.125f; }
                    __half h0 = __float2half_rn(f0);
                    __half h1 = __float2half_rn(f1);
                    __half l0 = __float2half_rn(f0 - __half2float(h0));
                    __half l1 = __float2half_rn(f1 - __half2float(h1));
                    __half2 hv = __halves2half2(h0, h1);
                    __half2 lv = __halves2half2(l0, l1);
                    const size_t rowb = ((size_t)(bb * HEADS + hd)) * SEQ + s;
                    if (wh == 0) {
                        __half* p = g_q + rowb * 128 + d;
                        *(__half2*)p        = hv;
                        *(__half2*)(p + 64) = lv;
                    } else if (wh == 1) {
                        __half* p = g_k + rowb * 192 + d;
                        *(__half2*)p         = hv;
                        *(__half2*)(p + 64)  = lv;
                        *(__half2*)(p + 128) = hv;
                    } else {
                        *(__half2*)(g_v + rowb * 64 + d) = hv;
                    }
                }
            }
        }
    }
}

// ---------------- flash attention: split scores, 2-stage cp.async ----------
#define SQ_STRIDE 136
#define SK_STRIDE 200
#define SV_STRIDE 72
#define FLASH_SMEM ((64 * SQ_STRIDE + 2 * 64 * SK_STRIDE + 2 * 64 * SV_STRIDE) * 2)  // 87040 B

__global__ __launch_bounds__(128) void flash_kernel()
{
    extern __shared__ __half fsm[];
    __half* sQ  = fsm;                                  // 64 x 136
    __half* sK0 = fsm + 64 * SQ_STRIDE;                 // 2 x (64 x 200)
    __half* sV0 = sK0 + 2 * 64 * SK_STRIDE;             // 2 x (64 x 72)

    const int tid = threadIdx.x, wid = tid >> 5, lane = tid & 31;
    const int qt = blockIdx.x, hh = blockIdx.y, bz = blockIdx.z;

    const size_t hrow = ((size_t)(bz * HEADS + hh)) * SEQ;
    const __half* Qg = g_q + (hrow + (size_t)qt * 64) * 128;
    const __half* Kg = g_k + hrow * 192;
    const __half* Vg = g_v + hrow * 64;

    // K/V loader indices
    const int krow = tid / 24 * 0;  // placeholder (computed per chunk below)
    (void)krow;

#define LOAD_KV(kt, stg) do {                                               \
        const __half* Kt_ = Kg + (size_t)(kt) * 64 * 192;                  \
        const __half* Vt_ = Vg + (size_t)(kt) * 64 * 64;                   \
        __half* sK_ = sK0 + (stg) * 64 * SK_STRIDE;                        \
        __half* sV_ = sV0 + (stg) * 64 * SV_STRIDE;                        \
        _Pragma("unroll")                                                   \
        for (int i_ = 0; i_ < 12; i_++) {                                  \
            int u_ = tid + i_ * 128;                                       \
            int r_ = u_ / 24, c_ = (u_ % 24) * 8;                          \
            cpa16(sK_ + r_ * SK_STRIDE + c_, Kt_ + (size_t)r_ * 192 + c_); \
        }                                                                   \
        _Pragma("unroll")                                                   \
        for (int i_ = 0; i_ < 4; i_++) {                                   \
            int u_ = tid + i_ * 128;                                       \
            int r_ = u_ >> 3, c_ = (u_ & 7) * 8;                           \
            cpa16(sV_ + r_ * SV_STRIDE + c_, Vt_ + (size_t)r_ * 64 + c_);  \
        }                                                                   \
        cp_commit();                                                       \
    } while (0)

    // Q tile (64 x 128) + first K/V tile
#pragma unroll
    for (int i = 0; i < 8; i++) {
        int u = tid + i * 128;
        int row = u >> 4, c = (u & 15) * 8;
        *(uint4*)(sQ + row * SQ_STRIDE + c) = *(const uint4*)(Qg + (size_t)row * 128 + c);
    }
    LOAD_KV(0, 0);
    __syncthreads();

    // hoist Q fragments: qf[0..3]=qh, qf[4..7]=ql
    uint32_t qf[8][4];
#pragma unroll
    for (int ks = 0; ks < 8; ks++)
        ldm_x4(qf[ks][0], qf[ks][1], qf[ks][2], qf[ks][3],
               smem_u32(sQ + (wid * 16 + (lane & 15)) * SQ_STRIDE + ks * 16 + (lane >> 4) * 8));

    float O[8][4];
#pragma unroll
    for (int dt = 0; dt < 8; dt++)
#pragma unroll
        for (int r = 0; r < 4; r++) O[dt][r] = 0.f;
    float mrow[2];
    float lrow[2];
    mrow[0] = -1e30f; mrow[1] = -1e30f;
    lrow[0] = 0.f;    lrow[1] = 0.f;

    const int qrow0 = wid * 16 + (lane >> 2);

    for (int kt = 0; kt <= qt; kt++) {
        cp_wait<0>();
        __syncthreads();
        if (kt < qt) LOAD_KV(kt + 1, (kt + 1) & 1);

        const __half* sK_ = sK0 + (kt & 1) * 64 * SK_STRIDE;
        const __half* sV_ = sV0 + (kt & 1) * 64 * SV_STRIDE;

        // ---- S = qh kh + qh kl + ql kh ----
        float S[8][4];
#pragma unroll
        for (int nt = 0; nt < 8; nt++)
#pragma unroll
            for (int r = 0; r < 4; r++) S[nt][r] = 0.f;

        const int klr = (lane >> 4) * 8 + (lane & 7);
        const int klc = ((lane >> 3) & 1) * 8;
#pragma unroll
        for (int ks = 0; ks < 12; ks++) {
            const int qi = (ks < 4) ? ks : (ks - 4);
#pragma unroll
            for (int jp = 0; jp < 4; jp++) {
                uint32_t b0, b1, b2, b3;
                ldm_x4(b0, b1, b2, b3,
                       smem_u32(sK_ + (jp * 16 + klr) * SK_STRIDE + ks * 16 + klc));
                mma16816(S[jp * 2 + 0], qf[qi][0], qf[qi][1], qf[qi][2], qf[qi][3], b0, b1);
                mma16816(S[jp * 2 + 1], qf[qi][0], qf[qi][1], qf[qi][2], qf[qi][3], b2, b3);
            }
        }

        // ---- causal mask on diagonal tile ----
        if (kt == qt) {
#pragma unroll
            for (int nt = 0; nt < 8; nt++) {
                const int jc = nt * 8 + 2 * (lane & 3);
#pragma unroll
                for (int ri = 0; ri < 2; ri++) {
                    const int ii = qrow0 + ri * 8;
                    if (jc     > ii) S[nt][ri * 2 + 0] = -1e30f;
                    if (jc + 1 > ii) S[nt][ri * 2 + 1] = -1e30f;
                }
            }
        }

        // ---- online softmax ----
#pragma unroll
        for (int ri = 0; ri < 2; ri++) {
            float tmax = -1e30f;
#pragma unroll
            for (int nt = 0; nt < 8; nt++)
                tmax = fmaxf(tmax, fmaxf(S[nt][ri * 2], S[nt][ri * 2 + 1]));
            tmax = fmaxf(tmax, __shfl_xor_sync(0xffffffffu, tmax, 1));
            tmax = fmaxf(tmax, __shfl_xor_sync(0xffffffffu, tmax, 2));
            const float mnew = fmaxf(mrow[ri], tmax);
            const float scale = __expf(mrow[ri] - mnew);
            float rs = 0.f;
#pragma unroll
            for (int nt = 0; nt < 8; nt++) {
                float p0 = __expf(S[nt][ri * 2 + 0] - mnew);
                float p1 = __expf(S[nt][ri * 2 + 1] - mnew);
                S[nt][ri * 2 + 0] = p0;
                S[nt][ri * 2 + 1] = p1;
                rs += p0 + p1;
            }
            rs += __shfl_xor_sync(0xffffffffu, rs, 1);
            rs += __shfl_xor_sync(0xffffffffu, rs, 2);
            lrow[ri] = lrow[ri] * scale + rs;
            mrow[ri] = mnew;
#pragma unroll
            for (int dt = 0; dt < 8; dt++) {
                O[dt][ri * 2 + 0] *= scale;
                O[dt][ri * 2 + 1] *= scale;
            }
        }

        // ---- O += P V ----
        const int vrow = lane & 15;
        const int vcol = (lane >> 4) * 8;
#pragma unroll
        for (int kk = 0; kk < 4; kk++) {
            uint32_t a0 = packh2(S[kk * 2 + 0][0], S[kk * 2 + 0][1]);
            uint32_t a1 = packh2(S[kk * 2 + 0][2], S[kk * 2 + 0][3]);
            uint32_t a2 = packh2(S[kk * 2 + 1][0], S[kk * 2 + 1][1]);
            uint32_t a3 = packh2(S[kk * 2 + 1][2], S[kk * 2 + 1][3]);
#pragma unroll
            for (int dp = 0; dp < 4; dp++) {
                uint32_t b0, b1, b2, b3;
                ldm_x4_t(b0, b1, b2, b3,
                         smem_u32(sV_ + (kk * 16 + vrow) * SV_STRIDE + dp * 16 + vcol));
                mma16816(O[dp * 2 + 0], a0, a1, a2, a3, b0, b1);
                mma16816(O[dp * 2 + 1], a0, a1, a2, a3, b2, b3);
            }
        }
    }
#undef LOAD_KV

    // ---- normalize + write ctx split [ch | ch | cl] ----
#pragma unroll
    for (int ri = 0; ri < 2; ri++) {
        const float inv = 1.f / lrow[ri];
        const size_t mg = (size_t)bz * SEQ + (size_t)qt * 64 + qrow0 + ri * 8;
#pragma unroll
        for (int dt = 0; dt < 8; dt++) {
            const int col = hh * 64 + dt * 8 + 2 * (lane & 3);
            float f0 = O[dt][ri * 2 + 0] * inv;
            float f1 = O[dt][ri * 2 + 1] * inv;
            __half h0 = __float2half_rn(f0);
            __half h1 = __float2half_rn(f1);
            __half l0 = __float2half_rn(f0 - __half2float(h0));
            __half l1 = __float2half_rn(f1 - __half2float(h1));
            __half2 hv = __halves2half2(h0, h1);
            __half2 lv = __halves2half2(l0, l1);
            __half* p = g_ctx + mg * K3 + col;
            *(__half2*)(p)        = hv;
            *(__half2*)(p + 1024) = hv;
            *(__half2*)(p + 2048) = lv;
        }
    }
}

// ---------------------------------------------------------------------------
extern "C" void kernel_launch(void* const* d_in, const int* in_sizes, int n_in,
                              void* d_out, int out_size)
{
    const float* x     = (const float*)d_in[0];
    const float* w_qkv = (const float*)d_in[1];
    const float* b_qkv = (const float*)d_in[2];
    const float* w_fc  = (const float*)d_in[3];
    const float* b_fc  = (const float*)d_in[4];
    float* out = (float*)d_out;

    static int attr_done = 0;
    if (!attr_done) {
        cudaFuncSetAttribute(hgemm_kernel<0>, cudaFuncAttributeMaxDynamicSharedMemorySize, HGEMM_SMEM);
        cudaFuncSetAttribute(hgemm_kernel<1>, cudaFuncAttributeMaxDynamicSharedMemorySize, HGEMM_SMEM);
        cudaFuncSetAttribute(flash_kernel, cudaFuncAttributeMaxDynamicSharedMemorySize, FLASH_SMEM);
        attr_done = 1;
    }

    split_kernel<0><<<MROWS * EMB / 2 / 256, 256>>>(x, MROWS, EMB);
    split_kernel<1><<<EMB * 3 * EMB / 2 / 256, 256>>>(w_qkv, EMB, 3 * EMB);
    split_kernel<2><<<EMB * EMB / 2 / 256, 256>>>(w_fc, EMB, EMB);

    // 1) QKV projection (split-precision fp16 tensor cores)
    hgemm_kernel<0><<<dim3(24, 64), 256, HGEMM_SMEM>>>(b_qkv, nullptr, 3 * EMB);

    // 2) causal flash attention (split-precision scores)
    flash_kernel<<<dim3(SEQ / 64, HEADS, BATCH), 128, FLASH_SMEM>>>();

    // 3) output projection
    hgemm_kernel<1><<<dim3(8, 64), 256, HGEMM_SMEM>>>(b_fc, out, EMB);
}

// round 5
// speedup vs baseline: 4.2379x; 1.3172x over previous
#include <cuda_runtime.h>
#include <cuda_fp16.h>
#include <math.h>
#include <stdint.h>

#define EMB 1024
#define HEADS 16
#define DH 64
#define BATCH 4
#define SEQ 2048
#define MROWS (BATCH * SEQ)   // 8192
#define K2 2048               // concatenated [hi|lo] K for projections

// ---------------- scratch (device globals; no runtime allocation) ----------
__device__ __half g_xA   [(size_t)MROWS * K2];        // [xh | xl]
__device__ __half g_wqkvB[(size_t)EMB * (3 * EMB)];   // wh (plain fp16)
__device__ __half g_wfcB [(size_t)EMB * EMB];         // wh
__device__ __half g_q    [(size_t)BATCH * HEADS * SEQ * 128];  // [qh | ql], pre-scaled 1/8
__device__ __half g_k    [(size_t)BATCH * HEADS * SEQ * 64];   // kh
__device__ __half g_v    [(size_t)BATCH * HEADS * SEQ * 64];
__device__ __half g_ctx  [(size_t)MROWS * K2];        // [ch | cl]

// ---------------- helpers --------------------------------------------------
__device__ __forceinline__ uint32_t smem_u32(const void* p) {
    return (uint32_t)__cvta_generic_to_shared(p);
}
__device__ __forceinline__ void ldm_x4(uint32_t& r0, uint32_t& r1, uint32_t& r2, uint32_t& r3, uint32_t addr) {
    asm volatile("ldmatrix.sync.aligned.m8n8.x4.shared.b16 { %0, %1, %2, %3 }, [ %4 ];"
                 : "=r"(r0), "=r"(r1), "=r"(r2), "=r"(r3) : "r"(addr));
}
__device__ __forceinline__ void ldm_x4_t(uint32_t& r0, uint32_t& r1, uint32_t& r2, uint32_t& r3, uint32_t addr) {
    asm volatile("ldmatrix.sync.aligned.m8n8.x4.trans.shared.b16 { %0, %1, %2, %3 }, [ %4 ];"
                 : "=r"(r0), "=r"(r1), "=r"(r2), "=r"(r3) : "r"(addr));
}
__device__ __forceinline__ void mma16816(float* c, uint32_t a0, uint32_t a1, uint32_t a2, uint32_t a3,
                                         uint32_t b0, uint32_t b1) {
    asm volatile("mma.sync.aligned.m16n8k16.row.col.f32.f16.f16.f32 "
                 "{ %0, %1, %2, %3 }, { %4, %5, %6, %7 }, { %8, %9 }, { %0, %1, %2, %3 };"
                 : "+f"(c[0]), "+f"(c[1]), "+f"(c[2]), "+f"(c[3])
                 : "r"(a0), "r"(a1), "r"(a2), "r"(a3), "r"(b0), "r"(b1));
}
__device__ __forceinline__ uint32_t packh2(float a, float b) {
    __half2 h = __floats2half2_rn(a, b);
    return *(uint32_t*)&h;
}
__device__ __forceinline__ void cpa16(void* s, const void* g) {
    asm volatile("cp.async.cg.shared.global [ %0 ], [ %1 ], 16;"
                 :: "r"(smem_u32(s)), "l"(g));
}
__device__ __forceinline__ void cp_commit() {
    asm volatile("cp.async.commit_group;");
}
template <int N>
__device__ __forceinline__ void cp_wait() {
    asm volatile("cp.async.wait_group %0;" :: "n"(N));
}

// ---------------- data prep -------------------------------------------------
// x -> [xh | xl] rows of width 2048
__global__ void splitx_kernel(const float* __restrict__ src) {
    size_t i = ((size_t)blockIdx.x * blockDim.x + threadIdx.x) * 2;
    float2 v = *(const float2*)(src + i);
    __half h0 = __float2half_rn(v.x);
    __half h1 = __float2half_rn(v.y);
    __half l0 = __float2half_rn(v.x - __half2float(h0));
    __half l1 = __float2half_rn(v.y - __half2float(h1));
    size_t r = i >> 10, c = i & 1023;
    __half* p = g_xA + r * K2 + c;
    *(__half2*)(p)        = __halves2half2(h0, h1);
    *(__half2*)(p + 1024) = __halves2half2(l0, l1);
}
// plain fp32 -> fp16 (weights)
template <int SEL>
__global__ void convert_kernel(const float* __restrict__ src) {
    __half* dst = (SEL == 0) ? g_wqkvB : g_wfcB;
    size_t i = ((size_t)blockIdx.x * blockDim.x + threadIdx.x) * 8;
    float4 f0 = *(const float4*)(src + i);
    float4 f1 = *(const float4*)(src + i + 4);
    __half2 h[4];
    h[0] = __floats2half2_rn(f0.x, f0.y);
    h[1] = __floats2half2_rn(f0.z, f0.w);
    h[2] = __floats2half2_rn(f1.x, f1.y);
    h[3] = __floats2half2_rn(f1.z, f1.w);
    *(uint4*)(dst + i) = *(uint4*)h;
}

// ---------------- HGEMM: 128x256 CTA tile, warp 64x64, K2=2048 -------------
#define GSTG 3
#define SA_ST (128 * 40)
#define SB_ST (32 * 264)
#define HGEMM_SMEM ((GSTG * (SA_ST + SB_ST)) * 2)   // 81408 B

template <int EPI>
__global__ __launch_bounds__(256, 1) void hgemm_kernel(
    const float* __restrict__ bias, float* __restrict__ C, int N)
{
    extern __shared__ __half hsm[];
    __half* sAbase = hsm;
    __half* sBbase = hsm + GSTG * SA_ST;

    const __half* __restrict__ A = (EPI == 0) ? g_xA : g_ctx;
    const __half* __restrict__ B = (EPI == 0) ? g_wqkvB : g_wfcB;

    const int tid = threadIdx.x;
    const int wid = tid >> 5, lane = tid & 31;
    const int wm = (wid >> 2) * 64;    // 0 / 64
    const int wn = (wid & 3) * 64;     // 0..192
    const int m0 = blockIdx.y * 128;
    const int n0 = blockIdx.x * 256;

    float acc[4][8][4];
#pragma unroll
    for (int mt = 0; mt < 4; mt++)
#pragma unroll
        for (int nt = 0; nt < 8; nt++)
#pragma unroll
            for (int r = 0; r < 4; r++) acc[mt][nt][r] = 0.f;

    const int ar0 = tid >> 2, ac0 = (tid & 3) * 8;    // A: 64 rows x 32 cols per pass
    const int br0 = tid >> 5, bc0 = (tid & 31) * 8;   // B: 8 rows x 256 cols per pass

    const __half* Ag0 = A + (size_t)(m0 + ar0) * K2 + ac0;
    const __half* Ag1 = A + (size_t)(m0 + ar0 + 64) * K2 + ac0;

#define LOAD_TILE(t, stg) do {                                                   \
        const int k0_ = (t) * 32;                                               \
        __half* sA_ = sAbase + (stg) * SA_ST;                                   \
        __half* sB_ = sBbase + (stg) * SB_ST;                                   \
        cpa16(sA_ + ar0 * 40 + ac0,        Ag0 + k0_);                          \
        cpa16(sA_ + (ar0 + 64) * 40 + ac0, Ag1 + k0_);                          \
        _Pragma("unroll")                                                        \
        for (int i_ = 0; i_ < 4; i_++) {                                        \
            const int br_ = br0 + i_ * 8;                                       \
            cpa16(sB_ + br_ * 264 + bc0,                                        \
                  B + (size_t)((k0_ + br_) & 1023) * N + n0 + bc0);             \
        }                                                                        \
        cp_commit();                                                            \
    } while (0)

    const int T = K2 / 32;    // 64
    LOAD_TILE(0, 0);
    LOAD_TILE(1, 1);

    int stg = 0;
    for (int t = 0; t < T; t++) {
        if (t < T - 1) cp_wait<1>(); else cp_wait<0>();
        __syncthreads();
        if (t + 2 < T) {
            int ns = stg + 2; if (ns >= GSTG) ns -= GSTG;
            LOAD_TILE(t + 2, ns);
        }
        __half* sA_ = sAbase + stg * SA_ST;
        __half* sB_ = sBbase + stg * SB_ST;
#pragma unroll
        for (int ks = 0; ks < 2; ks++) {
            uint32_t a[4][4];
#pragma unroll
            for (int mt = 0; mt < 4; mt++)
                ldm_x4(a[mt][0], a[mt][1], a[mt][2], a[mt][3],
                       smem_u32(sA_ + (wm + mt * 16 + (lane & 15)) * 40 + ks * 16 + (lane >> 4) * 8));
            uint32_t b[16];
#pragma unroll
            for (int nn = 0; nn < 4; nn++)
                ldm_x4_t(b[nn * 4 + 0], b[nn * 4 + 1], b[nn * 4 + 2], b[nn * 4 + 3],
                         smem_u32(sB_ + (ks * 16 + (lane & 15)) * 264 + wn + nn * 16 + (lane >> 4) * 8));
#pragma unroll
            for (int mt = 0; mt < 4; mt++)
#pragma unroll
                for (int nt = 0; nt < 8; nt++)
                    mma16816(acc[mt][nt], a[mt][0], a[mt][1], a[mt][2], a[mt][3],
                             b[nt * 2], b[nt * 2 + 1]);
        }
        stg++; if (stg >= GSTG) stg = 0;
    }
#undef LOAD_TILE

#pragma unroll
    for (int mt = 0; mt < 4; mt++) {
#pragma unroll
        for (int nt = 0; nt < 8; nt++) {
#pragma unroll
            for (int ri = 0; ri < 2; ri++) {
                const int m = m0 + wm + mt * 16 + (lane >> 2) + ri * 8;
                const int n = n0 + wn + nt * 8 + 2 * (lane & 3);
                float f0 = acc[mt][nt][ri * 2 + 0] + bias[n];
                float f1 = acc[mt][nt][ri * 2 + 1] + bias[n + 1];
                if (EPI == 1) {
                    float2 o;
                    o.x = f0;
                    o.y = f1;
                    *(float2*)(C + (size_t)m * N + n) = o;
                } else {
                    const int bb = m >> 11;
                    const int s  = m & 2047;
                    const int wh = n >> 10;
                    const int e  = n & 1023;
                    const int hd = e >> 6;
                    const int d  = e & 63;
                    const size_t rowb = ((size_t)(bb * HEADS + hd)) * SEQ + s;
                    if (wh == 0) {
                        f0 *= 0.125f; f1 *= 0.125f;
                        __half h0 = __float2half_rn(f0);
                        __half h1 = __float2half_rn(f1);
                        __half l0 = __float2half_rn(f0 - __half2float(h0));
                        __half l1 = __float2half_rn(f1 - __half2float(h1));
                        __half* p = g_q + rowb * 128 + d;
                        *(__half2*)p        = __halves2half2(h0, h1);
                        *(__half2*)(p + 64) = __halves2half2(l0, l1);
                    } else if (wh == 1) {
                        *(__half2*)(g_k + rowb * 64 + d) = __floats2half2_rn(f0, f1);
                    } else {
                        *(__half2*)(g_v + rowb * 64 + d) = __floats2half2_rn(f0, f1);
                    }
                }
            }
        }
    }
}

// ---------------- flash attention: S=(qh+ql)kh, 2-stage cp.async -----------
#define SQ_STRIDE 136
#define SK_STRIDE 72
#define SV_STRIDE 72
#define FLASH_SMEM ((64 * SQ_STRIDE + 2 * 64 * SK_STRIDE + 2 * 64 * SV_STRIDE) * 2)  // 54272 B

__global__ __launch_bounds__(128) void flash_kernel()
{
    extern __shared__ __half fsm[];
    __half* sQ  = fsm;                                  // 64 x 136 (128 cols data)
    __half* sK0 = fsm + 64 * SQ_STRIDE;                 // 2 x (64 x 72)
    __half* sV0 = sK0 + 2 * 64 * SK_STRIDE;             // 2 x (64 x 72)

    const int tid = threadIdx.x, wid = tid >> 5, lane = tid & 31;
    const int qt = blockIdx.x, hh = blockIdx.y, bz = blockIdx.z;

    const size_t hrow = ((size_t)(bz * HEADS + hh)) * SEQ;
    const __half* Qg = g_q + (hrow + (size_t)qt * 64) * 128;
    const __half* Kg = g_k + hrow * 64;
    const __half* Vg = g_v + hrow * 64;

#define LOAD_KV(kt, stg) do {                                               \
        const __half* Kt_ = Kg + (size_t)(kt) * 64 * 64;                   \
        const __half* Vt_ = Vg + (size_t)(kt) * 64 * 64;                   \
        __half* sK_ = sK0 + (stg) * 64 * SK_STRIDE;                        \
        __half* sV_ = sV0 + (stg) * 64 * SV_STRIDE;                        \
        _Pragma("unroll")                                                   \
        for (int i_ = 0; i_ < 4; i_++) {                                   \
            int u_ = tid + i_ * 128;                                       \
            int r_ = u_ >> 3, c_ = (u_ & 7) * 8;                           \
            cpa16(sK_ + r_ * SK_STRIDE + c_, Kt_ + (size_t)r_ * 64 + c_); \
            cpa16(sV_ + r_ * SV_STRIDE + c_, Vt_ + (size_t)r_ * 64 + c_); \
        }                                                                   \
        cp_commit();                                                       \
    } while (0)

    // Q tile (64 x 128) + first K/V tile
#pragma unroll
    for (int i = 0; i < 8; i++) {
        int u = tid + i * 128;
        int row = u >> 4, c = (u & 15) * 8;
        *(uint4*)(sQ + row * SQ_STRIDE + c) = *(const uint4*)(Qg + (size_t)row * 128 + c);
    }
    LOAD_KV(0, 0);
    __syncthreads();

    // hoist Q fragments: qf[0..3]=qh, qf[4..7]=ql
    uint32_t qf[8][4];
#pragma unroll
    for (int ks = 0; ks < 8; ks++)
        ldm_x4(qf[ks][0], qf[ks][1], qf[ks][2], qf[ks][3],
               smem_u32(sQ + (wid * 16 + (lane & 15)) * SQ_STRIDE + ks * 16 + (lane >> 4) * 8));

    float O[8][4];
#pragma unroll
    for (int dt = 0; dt < 8; dt++)
#pragma unroll
        for (int r = 0; r < 4; r++) O[dt][r] = 0.f;
    float mrow[2];
    float lrow[2];
    mrow[0] = -1e30f; mrow[1] = -1e30f;
    lrow[0] = 0.f;    lrow[1] = 0.f;

    const int qrow0 = wid * 16 + (lane >> 2);

    for (int kt = 0; kt <= qt; kt++) {
        cp_wait<0>();
        __syncthreads();
        if (kt < qt) LOAD_KV(kt + 1, (kt + 1) & 1);

        const __half* sK_ = sK0 + (kt & 1) * 64 * SK_STRIDE;
        const __half* sV_ = sV0 + (kt & 1) * 64 * SV_STRIDE;

        // ---- S = (qh + ql) kh : 8 k16 steps over sK's 64 cols ----
        float S[8][4];
#pragma unroll
        for (int nt = 0; nt < 8; nt++)
#pragma unroll
            for (int r = 0; r < 4; r++) S[nt][r] = 0.f;

        const int klr = (lane >> 4) * 8 + (lane & 7);
        const int klc = ((lane >> 3) & 1) * 8;
#pragma unroll
        for (int ks = 0; ks < 8; ks++) {
#pragma unroll
            for (int jp = 0; jp < 4; jp++) {
                uint32_t b0, b1, b2, b3;
                ldm_x4(b0, b1, b2, b3,
                       smem_u32(sK_ + (jp * 16 + klr) * SK_STRIDE + (ks & 3) * 16 + klc));
                mma16816(S[jp * 2 + 0], qf[ks][0], qf[ks][1], qf[ks][2], qf[ks][3], b0, b1);
                mma16816(S[jp * 2 + 1], qf[ks][0], qf[ks][1], qf[ks][2], qf[ks][3], b2, b3);
            }
        }

        // ---- causal mask on diagonal tile ----
        if (kt == qt) {
#pragma unroll
            for (int nt = 0; nt < 8; nt++) {
                const int jc = nt * 8 + 2 * (lane & 3);
#pragma unroll
                for (int ri = 0; ri < 2; ri++) {
                    const int ii = qrow0 + ri * 8;
                    if (jc     > ii) S[nt][ri * 2 + 0] = -1e30f;
                    if (jc + 1 > ii) S[nt][ri * 2 + 1] = -1e30f;
                }
            }
        }

        // ---- online softmax ----
#pragma unroll
        for (int ri = 0; ri < 2; ri++) {
            float tmax = -1e30f;
#pragma unroll
            for (int nt = 0; nt < 8; nt++)
                tmax = fmaxf(tmax, fmaxf(S[nt][ri * 2], S[nt][ri * 2 + 1]));
            tmax = fmaxf(tmax, __shfl_xor_sync(0xffffffffu, tmax, 1));
            tmax = fmaxf(tmax, __shfl_xor_sync(0xffffffffu, tmax, 2));
            const float mnew = fmaxf(mrow[ri], tmax);
            const float scale = __expf(mrow[ri] - mnew);
            float rs = 0.f;
#pragma unroll
            for (int nt = 0; nt < 8; nt++) {
                float p0 = __expf(S[nt][ri * 2 + 0] - mnew);
                float p1 = __expf(S[nt][ri * 2 + 1] - mnew);
                S[nt][ri * 2 + 0] = p0;
                S[nt][ri * 2 + 1] = p1;
                rs += p0 + p1;
            }
            rs += __shfl_xor_sync(0xffffffffu, rs, 1);
            rs += __shfl_xor_sync(0xffffffffu, rs, 2);
            lrow[ri] = lrow[ri] * scale + rs;
            mrow[ri] = mnew;
#pragma unroll
            for (int dt = 0; dt < 8; dt++) {
                O[dt][ri * 2 + 0] *= scale;
                O[dt][ri * 2 + 1] *= scale;
            }
        }

        // ---- O += P V ----
        const int vrow = lane & 15;
        const int vcol = (lane >> 4) * 8;
#pragma unroll
        for (int kk = 0; kk < 4; kk++) {
            uint32_t a0 = packh2(S[kk * 2 + 0][0], S[kk * 2 + 0][1]);
            uint32_t a1 = packh2(S[kk * 2 + 0][2], S[kk * 2 + 0][3]);
            uint32_t a2 = packh2(S[kk * 2 + 1][0], S[kk * 2 + 1][1]);
            uint32_t a3 = packh2(S[kk * 2 + 1][2], S[kk * 2 + 1][3]);
#pragma unroll
            for (int dp = 0; dp < 4; dp++) {
                uint32_t b0, b1, b2, b3;
                ldm_x4_t(b0, b1, b2, b3,
                         smem_u32(sV_ + (kk * 16 + vrow) * SV_STRIDE + dp * 16 + vcol));
                mma16816(O[dp * 2 + 0], a0, a1, a2, a3, b0, b1);
                mma16816(O[dp * 2 + 1], a0, a1, a2, a3, b2, b3);
            }
        }
    }
#undef LOAD_KV

    // ---- normalize + write ctx split [ch | cl] width 2048 ----
#pragma unroll
    for (int ri = 0; ri < 2; ri++) {
        const float inv = 1.f / lrow[ri];
        const size_t mg = (size_t)bz * SEQ + (size_t)qt * 64 + qrow0 + ri * 8;
#pragma unroll
        for (int dt = 0; dt < 8; dt++) {
            const int col = hh * 64 + dt * 8 + 2 * (lane & 3);
            float f0 = O[dt][ri * 2 + 0] * inv;
            float f1 = O[dt][ri * 2 + 1] * inv;
            __half h0 = __float2half_rn(f0);
            __half h1 = __float2half_rn(f1);
            __half l0 = __float2half_rn(f0 - __half2float(h0));
            __half l1 = __float2half_rn(f1 - __half2float(h1));
            __half* p = g_ctx + mg * K2 + col;
            *(__half2*)(p)        = __halves2half2(h0, h1);
            *(__half2*)(p + 1024) = __halves2half2(l0, l1);
        }
    }
}

// ---------------------------------------------------------------------------
extern "C" void kernel_launch(void* const* d_in, const int* in_sizes, int n_in,
                              void* d_out, int out_size)
{
    const float* x     = (const float*)d_in[0];
    const float* w_qkv = (const float*)d_in[1];
    const float* b_qkv = (const float*)d_in[2];
    const float* w_fc  = (const float*)d_in[3];
    const float* b_fc  = (const float*)d_in[4];
    float* out = (float*)d_out;

    static int attr_done = 0;
    if (!attr_done) {
        cudaFuncSetAttribute(hgemm_kernel<0>, cudaFuncAttributeMaxDynamicSharedMemorySize, HGEMM_SMEM);
        cudaFuncSetAttribute(hgemm_kernel<1>, cudaFuncAttributeMaxDynamicSharedMemorySize, HGEMM_SMEM);
        cudaFuncSetAttribute(flash_kernel, cudaFuncAttributeMaxDynamicSharedMemorySize, FLASH_SMEM);
        attr_done = 1;
    }

    splitx_kernel<<<MROWS * EMB / 2 / 256, 256>>>(x);
    convert_kernel<0><<<EMB * 3 * EMB / 8 / 256, 256>>>(w_qkv);
    convert_kernel<1><<<EMB * EMB / 8 / 256, 256>>>(w_fc);

    // 1) QKV projection: [xh|xl] @ [wh;wh] (K folded)
    hgemm_kernel<0><<<dim3(12, 64), 256, HGEMM_SMEM>>>(b_qkv, nullptr, 3 * EMB);

    // 2) causal flash attention
    flash_kernel<<<dim3(SEQ / 64, HEADS, BATCH), 128, FLASH_SMEM>>>();

    // 3) output projection: [ch|cl] @ [wh;wh]
    hgemm_kernel<1><<<dim3(4, 64), 256, HGEMM_SMEM>>>(b_fc, out, EMB);
}

// round 6
// speedup vs baseline: 5.3543x; 1.2634x over previous
#include <cuda_runtime.h>
#include <cuda_fp16.h>
#include <math.h>
#include <stdint.h>

#define EMB 1024
#define HEADS 16
#define DH 64
#define BATCH 4
#define SEQ 2048
#define MROWS (BATCH * SEQ)   // 8192
#define K2 2048               // concatenated [hi|lo] K for projections

// ---------------- scratch (device globals; no runtime allocation) ----------
__device__ __half g_xA   [(size_t)MROWS * K2];        // [xh | xl]
__device__ __half g_wqkvB[(size_t)EMB * (3 * EMB)];   // wh (plain fp16)
__device__ __half g_wfcB [(size_t)EMB * EMB];         // wh
__device__ __half g_q    [(size_t)BATCH * HEADS * SEQ * 128];  // [qh | ql], pre-scaled 1/8
__device__ __half g_k    [(size_t)BATCH * HEADS * SEQ * 64];   // kh
__device__ __half g_v    [(size_t)BATCH * HEADS * SEQ * 64];
__device__ __half g_ctx  [(size_t)MROWS * K2];        // [ch | cl]

// ---------------- helpers --------------------------------------------------
__device__ __forceinline__ uint32_t smem_u32(const void* p) {
    return (uint32_t)__cvta_generic_to_shared(p);
}
__device__ __forceinline__ void ldm_x4(uint32_t& r0, uint32_t& r1, uint32_t& r2, uint32_t& r3, uint32_t addr) {
    asm volatile("ldmatrix.sync.aligned.m8n8.x4.shared.b16 { %0, %1, %2, %3 }, [ %4 ];"
                 : "=r"(r0), "=r"(r1), "=r"(r2), "=r"(r3) : "r"(addr));
}
__device__ __forceinline__ void ldm_x4_t(uint32_t& r0, uint32_t& r1, uint32_t& r2, uint32_t& r3, uint32_t addr) {
    asm volatile("ldmatrix.sync.aligned.m8n8.x4.trans.shared.b16 { %0, %1, %2, %3 }, [ %4 ];"
                 : "=r"(r0), "=r"(r1), "=r"(r2), "=r"(r3) : "r"(addr));
}
__device__ __forceinline__ void mma16816(float* c, uint32_t a0, uint32_t a1, uint32_t a2, uint32_t a3,
                                         uint32_t b0, uint32_t b1) {
    asm volatile("mma.sync.aligned.m16n8k16.row.col.f32.f16.f16.f32 "
                 "{ %0, %1, %2, %3 }, { %4, %5, %6, %7 }, { %8, %9 }, { %0, %1, %2, %3 };"
                 : "+f"(c[0]), "+f"(c[1]), "+f"(c[2]), "+f"(c[3])
                 : "r"(a0), "r"(a1), "r"(a2), "r"(a3), "r"(b0), "r"(b1));
}
__device__ __forceinline__ uint32_t packh2(float a, float b) {
    __half2 h = __floats2half2_rn(a, b);
    return *(uint32_t*)&h;
}
__device__ __forceinline__ void cpa16(void* s, const void* g) {
    asm volatile("cp.async.cg.shared.global [ %0 ], [ %1 ], 16;"
                 :: "r"(smem_u32(s)), "l"(g));
}
__device__ __forceinline__ void cp_commit() {
    asm volatile("cp.async.commit_group;");
}
template <int N>
__device__ __forceinline__ void cp_wait() {
    asm volatile("cp.async.wait_group %0;" :: "n"(N));
}

// ---------------- data prep -------------------------------------------------
__global__ void splitx_kernel(const float* __restrict__ src) {
    size_t i = ((size_t)blockIdx.x * blockDim.x + threadIdx.x) * 2;
    float2 v = *(const float2*)(src + i);
    __half h0 = __float2half_rn(v.x);
    __half h1 = __float2half_rn(v.y);
    __half l0 = __float2half_rn(v.x - __half2float(h0));
    __half l1 = __float2half_rn(v.y - __half2float(h1));
    size_t r = i >> 10, c = i & 1023;
    __half* p = g_xA + r * K2 + c;
    *(__half2*)(p)        = __halves2half2(h0, h1);
    *(__half2*)(p + 1024) = __halves2half2(l0, l1);
}
template <int SEL>
__global__ void convert_kernel(const float* __restrict__ src) {
    __half* dst = (SEL == 0) ? g_wqkvB : g_wfcB;
    size_t i = ((size_t)blockIdx.x * blockDim.x + threadIdx.x) * 8;
    float4 f0 = *(const float4*)(src + i);
    float4 f1 = *(const float4*)(src + i + 4);
    __half2 h[4];
    h[0] = __floats2half2_rn(f0.x, f0.y);
    h[1] = __floats2half2_rn(f0.z, f0.w);
    h[2] = __floats2half2_rn(f1.x, f1.y);
    h[3] = __floats2half2_rn(f1.z, f1.w);
    *(uint4*)(dst + i) = *(uint4*)h;
}

// ---------------- HGEMM: 128x128 CTA, 4 warps of 64x64, 3-stage cp.async ---
#define GSTG 3
#define SA_ST (128 * 40)
#define SB_ST (32 * 136)
#define HGEMM_SMEM ((GSTG * (SA_ST + SB_ST)) * 2)   // 56832 B

template <int EPI>
__global__ __launch_bounds__(128, 2) void hgemm_kernel(
    const float* __restrict__ bias, float* __restrict__ C, int N)
{
    extern __shared__ __half hsm[];
    __half* sAbase = hsm;
    __half* sBbase = hsm + GSTG * SA_ST;

    const __half* __restrict__ A = (EPI == 0) ? g_xA : g_ctx;
    const __half* __restrict__ B = (EPI == 0) ? g_wqkvB : g_wfcB;

    const int tid = threadIdx.x;
    const int wid = tid >> 5, lane = tid & 31;
    const int wm = (wid & 1) * 64;
    const int wn = (wid >> 1) * 64;
    const int m0 = blockIdx.y * 128;
    const int n0 = blockIdx.x * 128;

    float acc[4][8][4];
#pragma unroll
    for (int mt = 0; mt < 4; mt++)
#pragma unroll
        for (int nt = 0; nt < 8; nt++)
#pragma unroll
            for (int r = 0; r < 4; r++) acc[mt][nt][r] = 0.f;

    // loaders (128 threads): A 128x32 (4 passes of 32 rows), B 32x128 (4 passes of 8 rows)
    const int ar0 = tid >> 2, ac0 = (tid & 3) * 8;
    const int br0 = tid >> 4, bc0 = (tid & 15) * 8;

#define LOAD_TILE(t, stg) do {                                                   \
        const int k0_ = (t) * 32;                                               \
        __half* sA_ = sAbase + (stg) * SA_ST;                                   \
        __half* sB_ = sBbase + (stg) * SB_ST;                                   \
        _Pragma("unroll")                                                        \
        for (int i_ = 0; i_ < 4; i_++) {                                        \
            const int r_ = ar0 + i_ * 32;                                       \
            cpa16(sA_ + r_ * 40 + ac0, A + (size_t)(m0 + r_) * K2 + k0_ + ac0); \
        }                                                                        \
        _Pragma("unroll")                                                        \
        for (int i_ = 0; i_ < 4; i_++) {                                        \
            const int r_ = br0 + i_ * 8;                                        \
            cpa16(sB_ + r_ * 136 + bc0,                                         \
                  B + (size_t)((k0_ + r_) & 1023) * N + n0 + bc0);              \
        }                                                                        \
        cp_commit();                                                            \
    } while (0)

    const int T = K2 / 32;    // 64
    LOAD_TILE(0, 0);
    LOAD_TILE(1, 1);

    int stg = 0;
    for (int t = 0; t < T; t++) {
        if (t < T - 1) cp_wait<1>(); else cp_wait<0>();
        __syncthreads();
        if (t + 2 < T) {
            int ns = stg + 2; if (ns >= GSTG) ns -= GSTG;
            LOAD_TILE(t + 2, ns);
        }
        __half* sA_ = sAbase + stg * SA_ST;
        __half* sB_ = sBbase + stg * SB_ST;
#pragma unroll
        for (int ks = 0; ks < 2; ks++) {
            uint32_t a[4][4];
#pragma unroll
            for (int mt = 0; mt < 4; mt++)
                ldm_x4(a[mt][0], a[mt][1], a[mt][2], a[mt][3],
                       smem_u32(sA_ + (wm + mt * 16 + (lane & 15)) * 40 + ks * 16 + (lane >> 4) * 8));
            uint32_t b[16];
#pragma unroll
            for (int nn = 0; nn < 4; nn++)
                ldm_x4_t(b[nn * 4 + 0], b[nn * 4 + 1], b[nn * 4 + 2], b[nn * 4 + 3],
                         smem_u32(sB_ + (ks * 16 + (lane & 15)) * 136 + wn + nn * 16 + (lane >> 4) * 8));
#pragma unroll
            for (int mt = 0; mt < 4; mt++)
#pragma unroll
                for (int nt = 0; nt < 8; nt++)
                    mma16816(acc[mt][nt], a[mt][0], a[mt][1], a[mt][2], a[mt][3],
                             b[nt * 2], b[nt * 2 + 1]);
        }
        stg++; if (stg >= GSTG) stg = 0;
    }
#undef LOAD_TILE

#pragma unroll
    for (int mt = 0; mt < 4; mt++) {
#pragma unroll
        for (int nt = 0; nt < 8; nt++) {
#pragma unroll
            for (int ri = 0; ri < 2; ri++) {
                const int m = m0 + wm + mt * 16 + (lane >> 2) + ri * 8;
                const int n = n0 + wn + nt * 8 + 2 * (lane & 3);
                float f0 = acc[mt][nt][ri * 2 + 0] + bias[n];
                float f1 = acc[mt][nt][ri * 2 + 1] + bias[n + 1];
                if (EPI == 1) {
                    float2 o;
                    o.x = f0;
                    o.y = f1;
                    *(float2*)(C + (size_t)m * N + n) = o;
                } else {
                    const int bb = m >> 11;
                    const int s  = m & 2047;
                    const int wh = n >> 10;
                    const int e  = n & 1023;
                    const int hd = e >> 6;
                    const int d  = e & 63;
                    const size_t rowb = ((size_t)(bb * HEADS + hd)) * SEQ + s;
                    if (wh == 0) {
                        f0 *= 0.125f; f1 *= 0.125f;
                        __half h0 = __float2half_rn(f0);
                        __half h1 = __float2half_rn(f1);
                        __half l0 = __float2half_rn(f0 - __half2float(h0));
                        __half l1 = __float2half_rn(f1 - __half2float(h1));
                        __half* p = g_q + rowb * 128 + d;
                        *(__half2*)p        = __halves2half2(h0, h1);
                        *(__half2*)(p + 64) = __halves2half2(l0, l1);
                    } else if (wh == 1) {
                        *(__half2*)(g_k + rowb * 64 + d) = __floats2half2_rn(f0, f1);
                    } else {
                        *(__half2*)(g_v + rowb * 64 + d) = __floats2half2_rn(f0, f1);
                    }
                }
            }
        }
    }
}

// ---------------- flash attention: S=(qh+ql)kh, 2-stage cp.async -----------
#define SQ_STRIDE 136
#define SK_STRIDE 72
#define SV_STRIDE 72
#define FLASH_SMEM ((64 * SQ_STRIDE + 2 * 64 * SK_STRIDE + 2 * 64 * SV_STRIDE) * 2)  // 54272 B

__global__ __launch_bounds__(128) void flash_kernel()
{
    extern __shared__ __half fsm[];
    __half* sQ  = fsm;                                  // 64 x 136 (128 cols data)
    __half* sK0 = fsm + 64 * SQ_STRIDE;                 // 2 x (64 x 72)
    __half* sV0 = sK0 + 2 * 64 * SK_STRIDE;             // 2 x (64 x 72)

    const int tid = threadIdx.x, wid = tid >> 5, lane = tid & 31;
    const int qt = blockIdx.x, hh = blockIdx.y, bz = blockIdx.z;

    const size_t hrow = ((size_t)(bz * HEADS + hh)) * SEQ;
    const __half* Qg = g_q + (hrow + (size_t)qt * 64) * 128;
    const __half* Kg = g_k + hrow * 64;
    const __half* Vg = g_v + hrow * 64;

#define LOAD_KV(kt, stg) do {                                               \
        const __half* Kt_ = Kg + (size_t)(kt) * 64 * 64;                   \
        const __half* Vt_ = Vg + (size_t)(kt) * 64 * 64;                   \
        __half* sK_ = sK0 + (stg) * 64 * SK_STRIDE;                        \
        __half* sV_ = sV0 + (stg) * 64 * SV_STRIDE;                        \
        _Pragma("unroll")                                                   \
        for (int i_ = 0; i_ < 4; i_++) {                                   \
            int u_ = tid + i_ * 128;                                       \
            int r_ = u_ >> 3, c_ = (u_ & 7) * 8;                           \
            cpa16(sK_ + r_ * SK_STRIDE + c_, Kt_ + (size_t)r_ * 64 + c_); \
            cpa16(sV_ + r_ * SV_STRIDE + c_, Vt_ + (size_t)r_ * 64 + c_); \
        }                                                                   \
        cp_commit();                                                       \
    } while (0)

    // Q tile (64 x 128) + first K/V tile
#pragma unroll
    for (int i = 0; i < 8; i++) {
        int u = tid + i * 128;
        int row = u >> 4, c = (u & 15) * 8;
        *(uint4*)(sQ + row * SQ_STRIDE + c) = *(const uint4*)(Qg + (size_t)row * 128 + c);
    }
    LOAD_KV(0, 0);
    __syncthreads();

    // hoist Q fragments: qf[0..3]=qh, qf[4..7]=ql
    uint32_t qf[8][4];
#pragma unroll
    for (int ks = 0; ks < 8; ks++)
        ldm_x4(qf[ks][0], qf[ks][1], qf[ks][2], qf[ks][3],
               smem_u32(sQ + (wid * 16 + (lane & 15)) * SQ_STRIDE + ks * 16 + (lane >> 4) * 8));

    float O[8][4];
#pragma unroll
    for (int dt = 0; dt < 8; dt++)
#pragma unroll
        for (int r = 0; r < 4; r++) O[dt][r] = 0.f;
    float mrow[2];
    float lrow[2];
    mrow[0] = -1e30f; mrow[1] = -1e30f;
    lrow[0] = 0.f;    lrow[1] = 0.f;

    const int qrow0 = wid * 16 + (lane >> 2);

    for (int kt = 0; kt <= qt; kt++) {
        cp_wait<0>();
        __syncthreads();
        if (kt < qt) LOAD_KV(kt + 1, (kt + 1) & 1);

        const __half* sK_ = sK0 + (kt & 1) * 64 * SK_STRIDE;
        const __half* sV_ = sV0 + (kt & 1) * 64 * SV_STRIDE;

        // ---- S = (qh + ql) kh ----
        float S[8][4];
#pragma unroll
        for (int nt = 0; nt < 8; nt++)
#pragma unroll
            for (int r = 0; r < 4; r++) S[nt][r] = 0.f;

        const int klr = (lane >> 4) * 8 + (lane & 7);
        const int klc = ((lane >> 3) & 1) * 8;
#pragma unroll
        for (int ks = 0; ks < 8; ks++) {
#pragma unroll
            for (int jp = 0; jp < 4; jp++) {
                uint32_t b0, b1, b2, b3;
                ldm_x4(b0, b1, b2, b3,
                       smem_u32(sK_ + (jp * 16 + klr) * SK_STRIDE + (ks & 3) * 16 + klc));
                mma16816(S[jp * 2 + 0], qf[ks][0], qf[ks][1], qf[ks][2], qf[ks][3], b0, b1);
                mma16816(S[jp * 2 + 1], qf[ks][0], qf[ks][1], qf[ks][2], qf[ks][3], b2, b3);
            }
        }

        // ---- causal mask on diagonal tile ----
        if (kt == qt) {
#pragma unroll
            for (int nt = 0; nt < 8; nt++) {
                const int jc = nt * 8 + 2 * (lane & 3);
#pragma unroll
                for (int ri = 0; ri < 2; ri++) {
                    const int ii = qrow0 + ri * 8;
                    if (jc     > ii) S[nt][ri * 2 + 0] = -1e30f;
                    if (jc + 1 > ii) S[nt][ri * 2 + 1] = -1e30f;
                }
            }
        }

        // ---- online softmax ----
#pragma unroll
        for (int ri = 0; ri < 2; ri++) {
            float tmax = -1e30f;
#pragma unroll
            for (int nt = 0; nt < 8; nt++)
                tmax = fmaxf(tmax, fmaxf(S[nt][ri * 2], S[nt][ri * 2 + 1]));
            tmax = fmaxf(tmax, __shfl_xor_sync(0xffffffffu, tmax, 1));
            tmax = fmaxf(tmax, __shfl_xor_sync(0xffffffffu, tmax, 2));
            const float mnew = fmaxf(mrow[ri], tmax);
            const float scale = __expf(mrow[ri] - mnew);
            float rs = 0.f;
#pragma unroll
            for (int nt = 0; nt < 8; nt++) {
                float p0 = __expf(S[nt][ri * 2 + 0] - mnew);
                float p1 = __expf(S[nt][ri * 2 + 1] - mnew);
                S[nt][ri * 2 + 0] = p0;
                S[nt][ri * 2 + 1] = p1;
                rs += p0 + p1;
            }
            rs += __shfl_xor_sync(0xffffffffu, rs, 1);
            rs += __shfl_xor_sync(0xffffffffu, rs, 2);
            lrow[ri] = lrow[ri] * scale + rs;
            mrow[ri] = mnew;
#pragma unroll
            for (int dt = 0; dt < 8; dt++) {
                O[dt][ri * 2 + 0] *= scale;
                O[dt][ri * 2 + 1] *= scale;
            }
        }

        // ---- O += P V ----
        const int vrow = lane & 15;
        const int vcol = (lane >> 4) * 8;
#pragma unroll
        for (int kk = 0; kk < 4; kk++) {
            uint32_t a0 = packh2(S[kk * 2 + 0][0], S[kk * 2 + 0][1]);
            uint32_t a1 = packh2(S[kk * 2 + 0][2], S[kk * 2 + 0][3]);
            uint32_t a2 = packh2(S[kk * 2 + 1][0], S[kk * 2 + 1][1]);
            uint32_t a3 = packh2(S[kk * 2 + 1][2], S[kk * 2 + 1][3]);
#pragma unroll
            for (int dp = 0; dp < 4; dp++) {
                uint32_t b0, b1, b2, b3;
                ldm_x4_t(b0, b1, b2, b3,
                         smem_u32(sV_ + (kk * 16 + vrow) * SV_STRIDE + dp * 16 + vcol));
                mma16816(O[dp * 2 + 0], a0, a1, a2, a3, b0, b1);
                mma16816(O[dp * 2 + 1], a0, a1, a2, a3, b2, b3);
            }
        }
    }
#undef LOAD_KV

    // ---- normalize + write ctx split [ch | cl] width 2048 ----
#pragma unroll
    for (int ri = 0; ri < 2; ri++) {
        const float inv = 1.f / lrow[ri];
        const size_t mg = (size_t)bz * SEQ + (size_t)qt * 64 + qrow0 + ri * 8;
#pragma unroll
        for (int dt = 0; dt < 8; dt++) {
            const int col = hh * 64 + dt * 8 + 2 * (lane & 3);
            float f0 = O[dt][ri * 2 + 0] * inv;
            float f1 = O[dt][ri * 2 + 1] * inv;
            __half h0 = __float2half_rn(f0);
            __half h1 = __float2half_rn(f1);
            __half l0 = __float2half_rn(f0 - __half2float(h0));
            __half l1 = __float2half_rn(f1 - __half2float(h1));
            __half* p = g_ctx + mg * K2 + col;
            *(__half2*)(p)        = __halves2half2(h0, h1);
            *(__half2*)(p + 1024) = __halves2half2(l0, l1);
        }
    }
}

// ---------------------------------------------------------------------------
extern "C" void kernel_launch(void* const* d_in, const int* in_sizes, int n_in,
                              void* d_out, int out_size)
{
    const float* x     = (const float*)d_in[0];
    const float* w_qkv = (const float*)d_in[1];
    const float* b_qkv = (const float*)d_in[2];
    const float* w_fc  = (const float*)d_in[3];
    const float* b_fc  = (const float*)d_in[4];
    float* out = (float*)d_out;

    static int attr_done = 0;
    if (!attr_done) {
        cudaFuncSetAttribute(hgemm_kernel<0>, cudaFuncAttributeMaxDynamicSharedMemorySize, HGEMM_SMEM);
        cudaFuncSetAttribute(hgemm_kernel<1>, cudaFuncAttributeMaxDynamicSharedMemorySize, HGEMM_SMEM);
        cudaFuncSetAttribute(flash_kernel, cudaFuncAttributeMaxDynamicSharedMemorySize, FLASH_SMEM);
        attr_done = 1;
    }

    splitx_kernel<<<MROWS * EMB / 2 / 256, 256>>>(x);
    convert_kernel<0><<<EMB * 3 * EMB / 8 / 256, 256>>>(w_qkv);
    convert_kernel<1><<<EMB * EMB / 8 / 256, 256>>>(w_fc);

    // 1) QKV projection: [xh|xl] @ [wh;wh] (K folded)
    hgemm_kernel<0><<<dim3(24, 64), 128, HGEMM_SMEM>>>(b_qkv, nullptr, 3 * EMB);

    // 2) causal flash attention
    flash_kernel<<<dim3(SEQ / 64, HEADS, BATCH), 128, FLASH_SMEM>>>();

    // 3) output projection: [ch|cl] @ [wh;wh]
    hgemm_kernel<1><<<dim3(8, 64), 128, HGEMM_SMEM>>>(b_fc, out, EMB);
}

// round 8
// speedup vs baseline: 6.0502x; 1.1300x over previous
#include <cuda_runtime.h>
#include <cuda_fp16.h>
#include <math.h>
#include <stdint.h>

#define EMB 1024
#define HEADS 16
#define DH 64
#define BATCH 4
#define SEQ 2048
#define MROWS (BATCH * SEQ)   // 8192

// ---------------- scratch (device globals; no runtime allocation) ----------
__device__ __half g_x    [(size_t)MROWS * EMB];       // x fp16
__device__ __half g_wqkvB[(size_t)EMB * (3 * EMB)];   // [k][n] fp16
__device__ __half g_wfcB [(size_t)EMB * EMB];         // [k][n] fp16
__device__ __half g_q    [(size_t)BATCH * HEADS * SEQ * 128];  // [qh | ql], pre-scaled 1/8
__device__ __half g_k    [(size_t)BATCH * HEADS * SEQ * 64];
__device__ __half g_v    [(size_t)BATCH * HEADS * SEQ * 64];
__device__ __half g_ctx  [(size_t)MROWS * EMB];       // attention out fp16

// ---------------- helpers --------------------------------------------------
__device__ __forceinline__ uint32_t smem_u32(const void* p) {
    return (uint32_t)__cvta_generic_to_shared(p);
}
__device__ __forceinline__ void ldm_x4(uint32_t& r0, uint32_t& r1, uint32_t& r2, uint32_t& r3, uint32_t addr) {
    asm volatile("ldmatrix.sync.aligned.m8n8.x4.shared.b16 { %0, %1, %2, %3 }, [ %4 ];"
                 : "=r"(r0), "=r"(r1), "=r"(r2), "=r"(r3) : "r"(addr));
}
__device__ __forceinline__ void ldm_x4_t(uint32_t& r0, uint32_t& r1, uint32_t& r2, uint32_t& r3, uint32_t addr) {
    asm volatile("ldmatrix.sync.aligned.m8n8.x4.trans.shared.b16 { %0, %1, %2, %3 }, [ %4 ];"
                 : "=r"(r0), "=r"(r1), "=r"(r2), "=r"(r3) : "r"(addr));
}
__device__ __forceinline__ void mma16816(float* c, uint32_t a0, uint32_t a1, uint32_t a2, uint32_t a3,
                                         uint32_t b0, uint32_t b1) {
    asm volatile("mma.sync.aligned.m16n8k16.row.col.f32.f16.f16.f32 "
                 "{ %0, %1, %2, %3 }, { %4, %5, %6, %7 }, { %8, %9 }, { %0, %1, %2, %3 };"
                 : "+f"(c[0]), "+f"(c[1]), "+f"(c[2]), "+f"(c[3])
                 : "r"(a0), "r"(a1), "r"(a2), "r"(a3), "r"(b0), "r"(b1));
}
__device__ __forceinline__ uint32_t packh2(float a, float b) {
    __half2 h = __floats2half2_rn(a, b);
    return *(uint32_t*)&h;
}
__device__ __forceinline__ void cpa16(void* s, const void* g) {
    asm volatile("cp.async.cg.shared.global [ %0 ], [ %1 ], 16;"
                 :: "r"(smem_u32(s)), "l"(g));
}
__device__ __forceinline__ void cp_commit() {
    asm volatile("cp.async.commit_group;");
}
template <int N>
__device__ __forceinline__ void cp_wait() {
    asm volatile("cp.async.wait_group %0;" :: "n"(N));
}

// ---------------- data prep: fp32 -> fp16 ----------------------------------
// SEL 0: w_qkv, SEL 1: w_fc, SEL 2: x
template <int SEL>
__global__ void convert_kernel(const float* __restrict__ src) {
    __half* dst = (SEL == 0) ? g_wqkvB : (SEL == 1) ? g_wfcB : g_x;
    size_t i = ((size_t)blockIdx.x * blockDim.x + threadIdx.x) * 8;
    float4 f0 = *(const float4*)(src + i);
    float4 f1 = *(const float4*)(src + i + 4);
    __half2 h[4];
    h[0] = __floats2half2_rn(f0.x, f0.y);
    h[1] = __floats2half2_rn(f0.z, f0.w);
    h[2] = __floats2half2_rn(f1.x, f1.y);
    h[3] = __floats2half2_rn(f1.z, f1.w);
    *(uint4*)(dst + i) = *(uint4*)h;
}

// ---------------- HGEMM: 128x128 CTA, 4 warps of 64x64, K=1024 -------------
// 3-stage cp.async pipeline, 64-K chunk per stage.
#define GSTG 3
#define SA_ST (128 * 72)
#define SB_ST (64 * 136)
#define HGEMM_SMEM ((GSTG * (SA_ST + SB_ST)) * 2)   // 107520 B

template <int EPI>
__global__ __launch_bounds__(128, 2) void hgemm_kernel(
    const float* __restrict__ bias, float* __restrict__ C, int N)
{
    extern __shared__ __half hsm[];
    __half* sAbase = hsm;
    __half* sBbase = hsm + GSTG * SA_ST;

    const __half* __restrict__ A = (EPI == 0) ? g_x : g_ctx;
    const __half* __restrict__ B = (EPI == 0) ? g_wqkvB : g_wfcB;

    const int tid = threadIdx.x;
    const int wid = tid >> 5, lane = tid & 31;
    const int wm = (wid & 1) * 64;
    const int wn = (wid >> 1) * 64;
    const int m0 = blockIdx.y * 128;
    const int n0 = blockIdx.x * 128;

    float acc[4][8][4];
#pragma unroll
    for (int mt = 0; mt < 4; mt++)
#pragma unroll
        for (int nt = 0; nt < 8; nt++)
#pragma unroll
            for (int r = 0; r < 4; r++) acc[mt][nt][r] = 0.f;

    const int br0 = tid >> 4, bc0 = (tid & 15) * 8;

#define LOAD_TILE(t, stg) do {                                                    \
        const int k0_ = (t) * 64;                                                \
        __half* sA_ = sAbase + (stg) * SA_ST;                                    \
        __half* sB_ = sBbase + (stg) * SB_ST;                                    \
        _Pragma("unroll")                                                         \
        for (int i_ = 0; i_ < 8; i_++)                                           \
            cpa16(sA_ + tid * 72 + i_ * 8,                                       \
                  A + (size_t)(m0 + tid) * EMB + k0_ + i_ * 8);                  \
        _Pragma("unroll")                                                         \
        for (int i_ = 0; i_ < 8; i_++) {                                         \
            const int r_ = br0 + i_ * 8;                                         \
            cpa16(sB_ + r_ * 136 + bc0,                                          \
                  B + (size_t)(k0_ + r_) * N + n0 + bc0);                        \
        }                                                                         \
        cp_commit();                                                             \
    } while (0)

    const int T = EMB / 64;    // 16
    LOAD_TILE(0, 0);
    LOAD_TILE(1, 1);

    int stg = 0;
    for (int t = 0; t < T; t++) {
        if (t < T - 1) cp_wait<1>(); else cp_wait<0>();
        __syncthreads();
        if (t + 2 < T) {
            int ns = stg + 2; if (ns >= GSTG) ns -= GSTG;
            LOAD_TILE(t + 2, ns);
        }
        __half* sA_ = sAbase + stg * SA_ST;
        __half* sB_ = sBbase + stg * SB_ST;
#pragma unroll
        for (int ks = 0; ks < 4; ks++) {
            uint32_t a[4][4];
#pragma unroll
            for (int mt = 0; mt < 4; mt++)
                ldm_x4(a[mt][0], a[mt][1], a[mt][2], a[mt][3],
                       smem_u32(sA_ + (wm + mt * 16 + (lane & 15)) * 72 + ks * 16 + (lane >> 4) * 8));
            uint32_t b[16];
#pragma unroll
            for (int nn = 0; nn < 4; nn++)
                ldm_x4_t(b[nn * 4 + 0], b[nn * 4 + 1], b[nn * 4 + 2], b[nn * 4 + 3],
                         smem_u32(sB_ + (ks * 16 + (lane & 15)) * 136 + wn + nn * 16 + (lane >> 4) * 8));
#pragma unroll
            for (int mt = 0; mt < 4; mt++)
#pragma unroll
                for (int nt = 0; nt < 8; nt++)
                    mma16816(acc[mt][nt], a[mt][0], a[mt][1], a[mt][2], a[mt][3],
                             b[nt * 2], b[nt * 2 + 1]);
        }
        stg++; if (stg >= GSTG) stg = 0;
    }
#undef LOAD_TILE

#pragma unroll
    for (int mt = 0; mt < 4; mt++) {
#pragma unroll
        for (int nt = 0; nt < 8; nt++) {
#pragma unroll
            for (int ri = 0; ri < 2; ri++) {
                const int m = m0 + wm + mt * 16 + (lane >> 2) + ri * 8;
                const int n = n0 + wn + nt * 8 + 2 * (lane & 3);
                float f0 = acc[mt][nt][ri * 2 + 0] + bias[n];
                float f1 = acc[mt][nt][ri * 2 + 1] + bias[n + 1];
                if (EPI == 1) {
                    float2 o;
                    o.x = f0;
                    o.y = f1;
                    *(float2*)(C + (size_t)m * N + n) = o;
                } else {
                    const int bb = m >> 11;
                    const int s  = m & 2047;
                    const int wh = n >> 10;
                    const int e  = n & 1023;
                    const int hd = e >> 6;
                    const int d  = e & 63;
                    const size_t rowb = ((size_t)(bb * HEADS + hd)) * SEQ + s;
                    if (wh == 0) {
                        f0 *= 0.125f; f1 *= 0.125f;
                        __half h0 = __float2half_rn(f0);
                        __half h1 = __float2half_rn(f1);
                        __half l0 = __float2half_rn(f0 - __half2float(h0));
                        __half l1 = __float2half_rn(f1 - __half2float(h1));
                        __half* p = g_q + rowb * 128 + d;
                        *(__half2*)p        = __halves2half2(h0, h1);
                        *(__half2*)(p + 64) = __halves2half2(l0, l1);
                    } else if (wh == 1) {
                        *(__half2*)(g_k + rowb * 64 + d) = __floats2half2_rn(f0, f1);
                    } else {
                        *(__half2*)(g_v + rowb * 64 + d) = __floats2half2_rn(f0, f1);
                    }
                }
            }
        }
    }
}

// ---------------- flash attention: S=(qh+ql)kh, 2-stage cp.async -----------
#define SQ_STRIDE 136
#define SK_STRIDE 72
#define SV_STRIDE 72
#define FLASH_SMEM ((64 * SQ_STRIDE + 2 * 64 * SK_STRIDE + 2 * 64 * SV_STRIDE) * 2)  // 54272 B

__global__ __launch_bounds__(128) void flash_kernel()
{
    extern __shared__ __half fsm[];
    __half* sQ  = fsm;
    __half* sK0 = fsm + 64 * SQ_STRIDE;
    __half* sV0 = sK0 + 2 * 64 * SK_STRIDE;

    const int tid = threadIdx.x, wid = tid >> 5, lane = tid & 31;
    const int qt = blockIdx.x, hh = blockIdx.y, bz = blockIdx.z;

    const size_t hrow = ((size_t)(bz * HEADS + hh)) * SEQ;
    const __half* Qg = g_q + (hrow + (size_t)qt * 64) * 128;
    const __half* Kg = g_k + hrow * 64;
    const __half* Vg = g_v + hrow * 64;

#define LOAD_KV(kt, stg) do {                                               \
        const __half* Kt_ = Kg + (size_t)(kt) * 64 * 64;                   \
        const __half* Vt_ = Vg + (size_t)(kt) * 64 * 64;                   \
        __half* sK_ = sK0 + (stg) * 64 * SK_STRIDE;                        \
        __half* sV_ = sV0 + (stg) * 64 * SV_STRIDE;                        \
        _Pragma("unroll")                                                   \
        for (int i_ = 0; i_ < 4; i_++) {                                   \
            int u_ = tid + i_ * 128;                                       \
            int r_ = u_ >> 3, c_ = (u_ & 7) * 8;                           \
            cpa16(sK_ + r_ * SK_STRIDE + c_, Kt_ + (size_t)r_ * 64 + c_); \
            cpa16(sV_ + r_ * SV_STRIDE + c_, Vt_ + (size_t)r_ * 64 + c_); \
        }                                                                   \
        cp_commit();                                                       \
    } while (0)

#pragma unroll
    for (int i = 0; i < 8; i++) {
        int u = tid + i * 128;
        int row = u >> 4, c = (u & 15) * 8;
        *(uint4*)(sQ + row * SQ_STRIDE + c) = *(const uint4*)(Qg + (size_t)row * 128 + c);
    }
    LOAD_KV(0, 0);
    __syncthreads();

    uint32_t qf[8][4];
#pragma unroll
    for (int ks = 0; ks < 8; ks++)
        ldm_x4(qf[ks][0], qf[ks][1], qf[ks][2], qf[ks][3],
               smem_u32(sQ + (wid * 16 + (lane & 15)) * SQ_STRIDE + ks * 16 + (lane >> 4) * 8));

    float O[8][4];
#pragma unroll
    for (int dt = 0; dt < 8; dt++)
#pragma unroll
        for (int r = 0; r < 4; r++) O[dt][r] = 0.f;
    float mrow[2];
    float lrow[2];
    mrow[0] = -1e30f; mrow[1] = -1e30f;
    lrow[0] = 0.f;    lrow[1] = 0.f;

    const int qrow0 = wid * 16 + (lane >> 2);

    for (int kt = 0; kt <= qt; kt++) {
        cp_wait<0>();
        __syncthreads();
        if (kt < qt) LOAD_KV(kt + 1, (kt + 1) & 1);

        const __half* sK_ = sK0 + (kt & 1) * 64 * SK_STRIDE;
        const __half* sV_ = sV0 + (kt & 1) * 64 * SV_STRIDE;

        float S[8][4];
#pragma unroll
        for (int nt = 0; nt < 8; nt++)
#pragma unroll
            for (int r = 0; r < 4; r++) S[nt][r] = 0.f;

        const int klr = (lane >> 4) * 8 + (lane & 7);
        const int klc = ((lane >> 3) & 1) * 8;
#pragma unroll
        for (int ks = 0; ks < 8; ks++) {
#pragma unroll
            for (int jp = 0; jp < 4; jp++) {
                uint32_t b0, b1, b2, b3;
                ldm_x4(b0, b1, b2, b3,
                       smem_u32(sK_ + (jp * 16 + klr) * SK_STRIDE + (ks & 3) * 16 + klc));
                mma16816(S[jp * 2 + 0], qf[ks][0], qf[ks][1], qf[ks][2], qf[ks][3], b0, b1);
                mma16816(S[jp * 2 + 1], qf[ks][0], qf[ks][1], qf[ks][2], qf[ks][3], b2, b3);
            }
        }

        if (kt == qt) {
#pragma unroll
            for (int nt = 0; nt < 8; nt++) {
                const int jc = nt * 8 + 2 * (lane & 3);
#pragma unroll
                for (int ri = 0; ri < 2; ri++) {
                    const int ii = qrow0 + ri * 8;
                    if (jc     > ii) S[nt][ri * 2 + 0] = -1e30f;
                    if (jc + 1 > ii) S[nt][ri * 2 + 1] = -1e30f;
                }
            }
        }

#pragma unroll
        for (int ri = 0; ri < 2; ri++) {
            float tmax = -1e30f;
#pragma unroll
            for (int nt = 0; nt < 8; nt++)
                tmax = fmaxf(tmax, fmaxf(S[nt][ri * 2], S[nt][ri * 2 + 1]));
            tmax = fmaxf(tmax, __shfl_xor_sync(0xffffffffu, tmax, 1));
            tmax = fmaxf(tmax, __shfl_xor_sync(0xffffffffu, tmax, 2));
            const float mnew = fmaxf(mrow[ri], tmax);
            const float scale = __expf(mrow[ri] - mnew);
            float rs = 0.f;
#pragma unroll
            for (int nt = 0; nt < 8; nt++) {
                float p0 = __expf(S[nt][ri * 2 + 0] - mnew);
                float p1 = __expf(S[nt][ri * 2 + 1] - mnew);
                S[nt][ri * 2 + 0] = p0;
                S[nt][ri * 2 + 1] = p1;
                rs += p0 + p1;
            }
            rs += __shfl_xor_sync(0xffffffffu, rs, 1);
            rs += __shfl_xor_sync(0xffffffffu, rs, 2);
            lrow[ri] = lrow[ri] * scale + rs;
            mrow[ri] = mnew;
#pragma unroll
            for (int dt = 0; dt < 8; dt++) {
                O[dt][ri * 2 + 0] *= scale;
                O[dt][ri * 2 + 1] *= scale;
            }
        }

        const int vrow = lane & 15;
        const int vcol = (lane >> 4) * 8;
#pragma unroll
        for (int kk = 0; kk < 4; kk++) {
            uint32_t a0 = packh2(S[kk * 2 + 0][0], S[kk * 2 + 0][1]);
            uint32_t a1 = packh2(S[kk * 2 + 0][2], S[kk * 2 + 0][3]);
            uint32_t a2 = packh2(S[kk * 2 + 1][0], S[kk * 2 + 1][1]);
            uint32_t a3 = packh2(S[kk * 2 + 1][2], S[kk * 2 + 1][3]);
#pragma unroll
            for (int dp = 0; dp < 4; dp++) {
                uint32_t b0, b1, b2, b3;
                ldm_x4_t(b0, b1, b2, b3,
                         smem_u32(sV_ + (kk * 16 + vrow) * SV_STRIDE + dp * 16 + vcol));
                mma16816(O[dp * 2 + 0], a0, a1, a2, a3, b0, b1);
                mma16816(O[dp * 2 + 1], a0, a1, a2, a3, b2, b3);
            }
        }
    }
#undef LOAD_KV

    // ---- normalize + write ctx fp16 [B*S, EMB] ----
#pragma unroll
    for (int ri = 0; ri < 2; ri++) {
        const float inv = 1.f / lrow[ri];
        const size_t mg = (size_t)bz * SEQ + (size_t)qt * 64 + qrow0 + ri * 8;
#pragma unroll
        for (int dt = 0; dt < 8; dt++) {
            const int col = hh * 64 + dt * 8 + 2 * (lane & 3);
            __half2 hv = __floats2half2_rn(O[dt][ri * 2 + 0] * inv, O[dt][ri * 2 + 1] * inv);
            *(__half2*)(g_ctx + mg * EMB + col) = hv;
        }
    }
}

// ---------------------------------------------------------------------------
extern "C" void kernel_launch(void* const* d_in, const int* in_sizes, int n_in,
                              void* d_out, int out_size)
{
    const float* x     = (const float*)d_in[0];
    const float* w_qkv = (const float*)d_in[1];
    const float* b_qkv = (const float*)d_in[2];
    const float* w_fc  = (const float*)d_in[3];
    const float* b_fc  = (const float*)d_in[4];
    float* out = (float*)d_out;

    static int attr_done = 0;
    if (!attr_done) {
        cudaFuncSetAttribute(hgemm_kernel<0>, cudaFuncAttributeMaxDynamicSharedMemorySize, HGEMM_SMEM);
        cudaFuncSetAttribute(hgemm_kernel<1>, cudaFuncAttributeMaxDynamicSharedMemorySize, HGEMM_SMEM);
        cudaFuncSetAttribute(flash_kernel, cudaFuncAttributeMaxDynamicSharedMemorySize, FLASH_SMEM);
        attr_done = 1;
    }

    convert_kernel<2><<<MROWS * EMB / 8 / 256, 256>>>(x);
    convert_kernel<0><<<EMB * 3 * EMB / 8 / 256, 256>>>(w_qkv);
    convert_kernel<1><<<EMB * EMB / 8 / 256, 256>>>(w_fc);

    // 1) QKV projection (fp16 tensor cores, K=1024)
    hgemm_kernel<0><<<dim3(24, 64), 128, HGEMM_SMEM>>>(b_qkv, nullptr, 3 * EMB);

    // 2) causal flash attention (split-q scores)
    flash_kernel<<<dim3(SEQ / 64, HEADS, BATCH), 128, FLASH_SMEM>>>();

    // 3) output projection (K=1024)
    hgemm_kernel<1><<<dim3(8, 64), 128, HGEMM_SMEM>>>(b_fc, out, EMB);
}

// round 9
// speedup vs baseline: 6.1239x; 1.0122x over previous
#include <cuda_runtime.h>
#include <cuda_fp16.h>
#include <math.h>
#include <stdint.h>

#define EMB 1024
#define HEADS 16
#define DH 64
#define BATCH 4
#define SEQ 2048
#define MROWS (BATCH * SEQ)   // 8192

// ---------------- scratch (device globals; no runtime allocation) ----------
__device__ __half g_x    [(size_t)MROWS * EMB];       // x fp16
__device__ __half g_wqkvB[(size_t)EMB * (3 * EMB)];   // [k][n] fp16
__device__ __half g_wfcB [(size_t)EMB * EMB];         // [k][n] fp16
__device__ __half g_qn   [(size_t)MROWS * 2048];      // [m][qh(1024) | ql(1024)], pre-scaled 1/8
__device__ __half g_kn   [(size_t)MROWS * EMB];       // [m][h*64+d]
__device__ __half g_vn   [(size_t)MROWS * EMB];
__device__ __half g_ctx  [(size_t)MROWS * EMB];       // attention out fp16

// ---------------- helpers --------------------------------------------------
__device__ __forceinline__ uint32_t smem_u32(const void* p) {
    return (uint32_t)__cvta_generic_to_shared(p);
}
__device__ __forceinline__ void ldm_x4(uint32_t& r0, uint32_t& r1, uint32_t& r2, uint32_t& r3, uint32_t addr) {
    asm volatile("ldmatrix.sync.aligned.m8n8.x4.shared.b16 { %0, %1, %2, %3 }, [ %4 ];"
                 : "=r"(r0), "=r"(r1), "=r"(r2), "=r"(r3) : "r"(addr));
}
__device__ __forceinline__ void ldm_x4_t(uint32_t& r0, uint32_t& r1, uint32_t& r2, uint32_t& r3, uint32_t addr) {
    asm volatile("ldmatrix.sync.aligned.m8n8.x4.trans.shared.b16 { %0, %1, %2, %3 }, [ %4 ];"
                 : "=r"(r0), "=r"(r1), "=r"(r2), "=r"(r3) : "r"(addr));
}
__device__ __forceinline__ void mma16816(float* c, uint32_t a0, uint32_t a1, uint32_t a2, uint32_t a3,
                                         uint32_t b0, uint32_t b1) {
    asm volatile("mma.sync.aligned.m16n8k16.row.col.f32.f16.f16.f32 "
                 "{ %0, %1, %2, %3 }, { %4, %5, %6, %7 }, { %8, %9 }, { %0, %1, %2, %3 };"
                 : "+f"(c[0]), "+f"(c[1]), "+f"(c[2]), "+f"(c[3])
                 : "r"(a0), "r"(a1), "r"(a2), "r"(a3), "r"(b0), "r"(b1));
}
__device__ __forceinline__ uint32_t packh2(float a, float b) {
    __half2 h = __floats2half2_rn(a, b);
    return *(uint32_t*)&h;
}
__device__ __forceinline__ void cpa16(void* s, const void* g) {
    asm volatile("cp.async.cg.shared.global [ %0 ], [ %1 ], 16;"
                 :: "r"(smem_u32(s)), "l"(g));
}
__device__ __forceinline__ void cp_commit() {
    asm volatile("cp.async.commit_group;");
}
template <int N>
__device__ __forceinline__ void cp_wait() {
    asm volatile("cp.async.wait_group %0;" :: "n"(N));
}

// ---------------- data prep: fp32 -> fp16 ----------------------------------
template <int SEL>
__global__ void convert_kernel(const float* __restrict__ src) {
    __half* dst = (SEL == 0) ? g_wqkvB : (SEL == 1) ? g_wfcB : g_x;
    size_t i = ((size_t)blockIdx.x * blockDim.x + threadIdx.x) * 8;
    float4 f0 = *(const float4*)(src + i);
    float4 f1 = *(const float4*)(src + i + 4);
    __half2 h[4];
    h[0] = __floats2half2_rn(f0.x, f0.y);
    h[1] = __floats2half2_rn(f0.z, f0.w);
    h[2] = __floats2half2_rn(f1.x, f1.y);
    h[3] = __floats2half2_rn(f1.z, f1.w);
    *(uint4*)(dst + i) = *(uint4*)h;
}

// ---------------- HGEMM: 128x128 CTA, 4 warps of 64x64, K=1024 -------------
#define GSTG 3
#define SA_ST (128 * 72)
#define SB_ST (64 * 136)
#define HGEMM_SMEM ((GSTG * (SA_ST + SB_ST)) * 2)   // 107520 B

template <int EPI>
__global__ __launch_bounds__(128, 2) void hgemm_kernel(
    const float* __restrict__ bias, float* __restrict__ C, int N)
{
    extern __shared__ __half hsm[];
    __half* sAbase = hsm;
    __half* sBbase = hsm + GSTG * SA_ST;

    const __half* __restrict__ A = (EPI == 0) ? g_x : g_ctx;
    const __half* __restrict__ B = (EPI == 0) ? g_wqkvB : g_wfcB;

    const int tid = threadIdx.x;
    const int wid = tid >> 5, lane = tid & 31;
    const int wm = (wid & 1) * 64;
    const int wn = (wid >> 1) * 64;
    const int m0 = blockIdx.y * 128;
    const int n0 = blockIdx.x * 128;

    float acc[4][8][4];
#pragma unroll
    for (int mt = 0; mt < 4; mt++)
#pragma unroll
        for (int nt = 0; nt < 8; nt++)
#pragma unroll
            for (int r = 0; r < 4; r++) acc[mt][nt][r] = 0.f;

    const int br0 = tid >> 4, bc0 = (tid & 15) * 8;

#define LOAD_TILE(t, stg) do {                                                    \
        const int k0_ = (t) * 64;                                                \
        __half* sA_ = sAbase + (stg) * SA_ST;                                    \
        __half* sB_ = sBbase + (stg) * SB_ST;                                    \
        _Pragma("unroll")                                                         \
        for (int i_ = 0; i_ < 8; i_++)                                           \
            cpa16(sA_ + tid * 72 + i_ * 8,                                       \
                  A + (size_t)(m0 + tid) * EMB + k0_ + i_ * 8);                  \
        _Pragma("unroll")                                                         \
        for (int i_ = 0; i_ < 8; i_++) {                                         \
            const int r_ = br0 + i_ * 8;                                         \
            cpa16(sB_ + r_ * 136 + bc0,                                          \
                  B + (size_t)(k0_ + r_) * N + n0 + bc0);                        \
        }                                                                         \
        cp_commit();                                                             \
    } while (0)

    const int T = EMB / 64;    // 16
    LOAD_TILE(0, 0);
    LOAD_TILE(1, 1);

    int stg = 0;
    for (int t = 0; t < T; t++) {
        if (t < T - 1) cp_wait<1>(); else cp_wait<0>();
        __syncthreads();
        if (t + 2 < T) {
            int ns = stg + 2; if (ns >= GSTG) ns -= GSTG;
            LOAD_TILE(t + 2, ns);
        }
        __half* sA_ = sAbase + stg * SA_ST;
        __half* sB_ = sBbase + stg * SB_ST;
#pragma unroll
        for (int ks = 0; ks < 4; ks++) {
            uint32_t a[4][4];
#pragma unroll
            for (int mt = 0; mt < 4; mt++)
                ldm_x4(a[mt][0], a[mt][1], a[mt][2], a[mt][3],
                       smem_u32(sA_ + (wm + mt * 16 + (lane & 15)) * 72 + ks * 16 + (lane >> 4) * 8));
            uint32_t b[16];
#pragma unroll
            for (int nn = 0; nn < 4; nn++)
                ldm_x4_t(b[nn * 4 + 0], b[nn * 4 + 1], b[nn * 4 + 2], b[nn * 4 + 3],
                         smem_u32(sB_ + (ks * 16 + (lane & 15)) * 136 + wn + nn * 16 + (lane >> 4) * 8));
#pragma unroll
            for (int mt = 0; mt < 4; mt++)
#pragma unroll
                for (int nt = 0; nt < 8; nt++)
                    mma16816(acc[mt][nt], a[mt][0], a[mt][1], a[mt][2], a[mt][3],
                             b[nt * 2], b[nt * 2 + 1]);
        }
        stg++; if (stg >= GSTG) stg = 0;
    }
#undef LOAD_TILE

#pragma unroll
    for (int mt = 0; mt < 4; mt++) {
#pragma unroll
        for (int nt = 0; nt < 8; nt++) {
#pragma unroll
            for (int ri = 0; ri < 2; ri++) {
                const int m = m0 + wm + mt * 16 + (lane >> 2) + ri * 8;
                const int n = n0 + wn + nt * 8 + 2 * (lane & 3);
                float f0 = acc[mt][nt][ri * 2 + 0] + bias[n];
                float f1 = acc[mt][nt][ri * 2 + 1] + bias[n + 1];
                if (EPI == 1) {
                    float2 o;
                    o.x = f0;
                    o.y = f1;
                    *(float2*)(C + (size_t)m * N + n) = o;
                } else {
                    // natural-layout coalesced QKV stores
                    const int wh = n >> 10;     // 0=q 1=k 2=v
                    const int e  = n & 1023;
                    if (wh == 0) {
                        f0 *= 0.125f; f1 *= 0.125f;
                        __half h0 = __float2half_rn(f0);
                        __half h1 = __float2half_rn(f1);
                        __half l0 = __float2half_rn(f0 - __half2float(h0));
                        __half l1 = __float2half_rn(f1 - __half2float(h1));
                        __half* p = g_qn + (size_t)m * 2048 + e;
                        *(__half2*)p          = __halves2half2(h0, h1);
                        *(__half2*)(p + 1024) = __halves2half2(l0, l1);
                    } else if (wh == 1) {
                        *(__half2*)(g_kn + (size_t)m * EMB + e) = __floats2half2_rn(f0, f1);
                    } else {
                        *(__half2*)(g_vn + (size_t)m * EMB + e) = __floats2half2_rn(f0, f1);
                    }
                }
            }
        }
    }
}

// ---------------- flash attention: S=(qh+ql)kh, 2-stage cp.async -----------
#define SQ_STRIDE 136
#define SK_STRIDE 72
#define SV_STRIDE 72
#define FLASH_SMEM ((64 * SQ_STRIDE + 2 * 64 * SK_STRIDE + 2 * 64 * SV_STRIDE) * 2)  // 54272 B

__global__ __launch_bounds__(128) void flash_kernel()
{
    extern __shared__ __half fsm[];
    __half* sQ  = fsm;
    __half* sK0 = fsm + 64 * SQ_STRIDE;
    __half* sV0 = sK0 + 2 * 64 * SK_STRIDE;

    const int tid = threadIdx.x, wid = tid >> 5, lane = tid & 31;
    const int qt = blockIdx.x, hh = blockIdx.y, bz = blockIdx.z;

    const size_t mbase = (size_t)bz * SEQ;
    const __half* Qg = g_qn + (mbase + (size_t)qt * 64) * 2048 + hh * 64;   // qh; ql at +1024
    const __half* Kg = g_kn + mbase * EMB + hh * 64;                        // row stride EMB
    const __half* Vg = g_vn + mbase * EMB + hh * 64;

#define LOAD_KV(kt, stg) do {                                               \
        const __half* Kt_ = Kg + (size_t)(kt) * 64 * EMB;                  \
        const __half* Vt_ = Vg + (size_t)(kt) * 64 * EMB;                  \
        __half* sK_ = sK0 + (stg) * 64 * SK_STRIDE;                        \
        __half* sV_ = sV0 + (stg) * 64 * SV_STRIDE;                        \
        _Pragma("unroll")                                                   \
        for (int i_ = 0; i_ < 4; i_++) {                                   \
            int u_ = tid + i_ * 128;                                       \
            int r_ = u_ >> 3, c_ = (u_ & 7) * 8;                           \
            cpa16(sK_ + r_ * SK_STRIDE + c_, Kt_ + (size_t)r_ * EMB + c_); \
            cpa16(sV_ + r_ * SV_STRIDE + c_, Vt_ + (size_t)r_ * EMB + c_); \
        }                                                                   \
        cp_commit();                                                       \
    } while (0)

    // Q tile: cols 0..63 = qh, 64..127 = ql
#pragma unroll
    for (int i = 0; i < 8; i++) {
        int u = tid + i * 128;
        int row = u >> 4, seg = u & 15;
        const __half* src = (seg < 8)
            ? (Qg + (size_t)row * 2048 + seg * 8)
            : (Qg + (size_t)row * 2048 + 1024 + (seg - 8) * 8);
        *(uint4*)(sQ + row * SQ_STRIDE + seg * 8) = *(const uint4*)src;
    }
    LOAD_KV(0, 0);
    __syncthreads();

    uint32_t qf[8][4];
#pragma unroll
    for (int ks = 0; ks < 8; ks++)
        ldm_x4(qf[ks][0], qf[ks][1], qf[ks][2], qf[ks][3],
               smem_u32(sQ + (wid * 16 + (lane & 15)) * SQ_STRIDE + ks * 16 + (lane >> 4) * 8));

    float O[8][4];
#pragma unroll
    for (int dt = 0; dt < 8; dt++)
#pragma unroll
        for (int r = 0; r < 4; r++) O[dt][r] = 0.f;
    float mrow[2];
    float lrow[2];
    mrow[0] = -1e30f; mrow[1] = -1e30f;
    lrow[0] = 0.f;    lrow[1] = 0.f;

    const int qrow0 = wid * 16 + (lane >> 2);

    for (int kt = 0; kt <= qt; kt++) {
        cp_wait<0>();
        __syncthreads();
        if (kt < qt) LOAD_KV(kt + 1, (kt + 1) & 1);

        const __half* sK_ = sK0 + (kt & 1) * 64 * SK_STRIDE;
        const __half* sV_ = sV0 + (kt & 1) * 64 * SV_STRIDE;

        float S[8][4];
#pragma unroll
        for (int nt = 0; nt < 8; nt++)
#pragma unroll
            for (int r = 0; r < 4; r++) S[nt][r] = 0.f;

        const int klr = (lane >> 4) * 8 + (lane & 7);
        const int klc = ((lane >> 3) & 1) * 8;
#pragma unroll
        for (int ks = 0; ks < 8; ks++) {
#pragma unroll
            for (int jp = 0; jp < 4; jp++) {
                uint32_t b0, b1, b2, b3;
                ldm_x4(b0, b1, b2, b3,
                       smem_u32(sK_ + (jp * 16 + klr) * SK_STRIDE + (ks & 3) * 16 + klc));
                mma16816(S[jp * 2 + 0], qf[ks][0], qf[ks][1], qf[ks][2], qf[ks][3], b0, b1);
                mma16816(S[jp * 2 + 1], qf[ks][0], qf[ks][1], qf[ks][2], qf[ks][3], b2, b3);
            }
        }

        if (kt == qt) {
#pragma unroll
            for (int nt = 0; nt < 8; nt++) {
                const int jc = nt * 8 + 2 * (lane & 3);
#pragma unroll
                for (int ri = 0; ri < 2; ri++) {
                    const int ii = qrow0 + ri * 8;
                    if (jc     > ii) S[nt][ri * 2 + 0] = -1e30f;
                    if (jc + 1 > ii) S[nt][ri * 2 + 1] = -1e30f;
                }
            }
        }

#pragma unroll
        for (int ri = 0; ri < 2; ri++) {
            float tmax = -1e30f;
#pragma unroll
            for (int nt = 0; nt < 8; nt++)
                tmax = fmaxf(tmax, fmaxf(S[nt][ri * 2], S[nt][ri * 2 + 1]));
            tmax = fmaxf(tmax, __shfl_xor_sync(0xffffffffu, tmax, 1));
            tmax = fmaxf(tmax, __shfl_xor_sync(0xffffffffu, tmax, 2));
            const float mnew = fmaxf(mrow[ri], tmax);
            const float scale = __expf(mrow[ri] - mnew);
            float rs = 0.f;
#pragma unroll
            for (int nt = 0; nt < 8; nt++) {
                float p0 = __expf(S[nt][ri * 2 + 0] - mnew);
                float p1 = __expf(S[nt][ri * 2 + 1] - mnew);
                S[nt][ri * 2 + 0] = p0;
                S[nt][ri * 2 + 1] = p1;
                rs += p0 + p1;
            }
            rs += __shfl_xor_sync(0xffffffffu, rs, 1);
            rs += __shfl_xor_sync(0xffffffffu, rs, 2);
            lrow[ri] = lrow[ri] * scale + rs;
            mrow[ri] = mnew;
#pragma unroll
            for (int dt = 0; dt < 8; dt++) {
                O[dt][ri * 2 + 0] *= scale;
                O[dt][ri * 2 + 1] *= scale;
            }
        }

        const int vrow = lane & 15;
        const int vcol = (lane >> 4) * 8;
#pragma unroll
        for (int kk = 0; kk < 4; kk++) {
            uint32_t a0 = packh2(S[kk * 2 + 0][0], S[kk * 2 + 0][1]);
            uint32_t a1 = packh2(S[kk * 2 + 0][2], S[kk * 2 + 0][3]);
            uint32_t a2 = packh2(S[kk * 2 + 1][0], S[kk * 2 + 1][1]);
            uint32_t a3 = packh2(S[kk * 2 + 1][2], S[kk * 2 + 1][3]);
#pragma unroll
            for (int dp = 0; dp < 4; dp++) {
                uint32_t b0, b1, b2, b3;
                ldm_x4_t(b0, b1, b2, b3,
                         smem_u32(sV_ + (kk * 16 + vrow) * SV_STRIDE + dp * 16 + vcol));
                mma16816(O[dp * 2 + 0], a0, a1, a2, a3, b0, b1);
                mma16816(O[dp * 2 + 1], a0, a1, a2, a3, b2, b3);
            }
        }
    }
#undef LOAD_KV

    // ---- normalize + write ctx fp16 [B*S, EMB] ----
#pragma unroll
    for (int ri = 0; ri < 2; ri++) {
        const float inv = 1.f / lrow[ri];
        const size_t mg = mbase + (size_t)qt * 64 + qrow0 + ri * 8;
#pragma unroll
        for (int dt = 0; dt < 8; dt++) {
            const int col = hh * 64 + dt * 8 + 2 * (lane & 3);
            __half2 hv = __floats2half2_rn(O[dt][ri * 2 + 0] * inv, O[dt][ri * 2 + 1] * inv);
            *(__half2*)(g_ctx + mg * EMB + col) = hv;
        }
    }
}

// ---------------------------------------------------------------------------
extern "C" void kernel_launch(void* const* d_in, const int* in_sizes, int n_in,
                              void* d_out, int out_size)
{
    const float* x     = (const float*)d_in[0];
    const float* w_qkv = (const float*)d_in[1];
    const float* b_qkv = (const float*)d_in[2];
    const float* w_fc  = (const float*)d_in[3];
    const float* b_fc  = (const float*)d_in[4];
    float* out = (float*)d_out;

    static int attr_done = 0;
    if (!attr_done) {
        cudaFuncSetAttribute(hgemm_kernel<0>, cudaFuncAttributeMaxDynamicSharedMemorySize, HGEMM_SMEM);
        cudaFuncSetAttribute(hgemm_kernel<1>, cudaFuncAttributeMaxDynamicSharedMemorySize, HGEMM_SMEM);
        cudaFuncSetAttribute(flash_kernel, cudaFuncAttributeMaxDynamicSharedMemorySize, FLASH_SMEM);
        attr_done = 1;
    }

    convert_kernel<2><<<MROWS * EMB / 8 / 256, 256>>>(x);
    convert_kernel<0><<<EMB * 3 * EMB / 8 / 256, 256>>>(w_qkv);
    convert_kernel<1><<<EMB * EMB / 8 / 256, 256>>>(w_fc);

    // 1) QKV projection (fp16 tensor cores, coalesced natural-layout stores)
    hgemm_kernel<0><<<dim3(24, 64), 128, HGEMM_SMEM>>>(b_qkv, nullptr, 3 * EMB);

    // 2) causal flash attention (strided natural-layout loads)
    flash_kernel<<<dim3(SEQ / 64, HEADS, BATCH), 128, FLASH_SMEM>>>();

    // 3) output projection (K=1024)
    hgemm_kernel<1><<<dim3(8, 64), 128, HGEMM_SMEM>>>(b_fc, out, EMB);
}

// round 10
// speedup vs baseline: 7.6909x; 1.2559x over previous
#include <cuda_runtime.h>
#include <cuda_fp16.h>
#include <math.h>
#include <stdint.h>

#define EMB 1024
#define HEADS 16
#define DH 64
#define BATCH 4
#define SEQ 2048
#define MROWS (BATCH * SEQ)   // 8192

// ---------------- scratch (device globals; no runtime allocation) ----------
__device__ __half g_x    [(size_t)MROWS * EMB];       // x fp16
__device__ __half g_wqkvB[(size_t)EMB * (3 * EMB)];   // [k][n] fp16
__device__ __half g_wfcB [(size_t)EMB * EMB];         // [k][n] fp16
__device__ __half g_qn   [(size_t)MROWS * 2048];      // [m][qh(1024) | ql(1024)], pre-scaled 1/8
__device__ __half g_kn   [(size_t)MROWS * EMB];       // [m][h*64+d]
__device__ __half g_vn   [(size_t)MROWS * EMB];
__device__ __half g_ctx  [(size_t)MROWS * EMB];       // attention out fp16

// ---------------- helpers --------------------------------------------------
__device__ __forceinline__ uint32_t smem_u32(const void* p) {
    return (uint32_t)__cvta_generic_to_shared(p);
}
__device__ __forceinline__ void ldm_x4(uint32_t& r0, uint32_t& r1, uint32_t& r2, uint32_t& r3, uint32_t addr) {
    asm volatile("ldmatrix.sync.aligned.m8n8.x4.shared.b16 { %0, %1, %2, %3 }, [ %4 ];"
                 : "=r"(r0), "=r"(r1), "=r"(r2), "=r"(r3) : "r"(addr));
}
__device__ __forceinline__ void ldm_x4_t(uint32_t& r0, uint32_t& r1, uint32_t& r2, uint32_t& r3, uint32_t addr) {
    asm volatile("ldmatrix.sync.aligned.m8n8.x4.trans.shared.b16 { %0, %1, %2, %3 }, [ %4 ];"
                 : "=r"(r0), "=r"(r1), "=r"(r2), "=r"(r3) : "r"(addr));
}
__device__ __forceinline__ void mma16816(float* c, uint32_t a0, uint32_t a1, uint32_t a2, uint32_t a3,
                                         uint32_t b0, uint32_t b1) {
    asm volatile("mma.sync.aligned.m16n8k16.row.col.f32.f16.f16.f32 "
                 "{ %0, %1, %2, %3 }, { %4, %5, %6, %7 }, { %8, %9 }, { %0, %1, %2, %3 };"
                 : "+f"(c[0]), "+f"(c[1]), "+f"(c[2]), "+f"(c[3])
                 : "r"(a0), "r"(a1), "r"(a2), "r"(a3), "r"(b0), "r"(b1));
}
__device__ __forceinline__ uint32_t packh2(float a, float b) {
    __half2 h = __floats2half2_rn(a, b);
    return *(uint32_t*)&h;
}
__device__ __forceinline__ void cpa16(void* s, const void* g) {
    asm volatile("cp.async.cg.shared.global [ %0 ], [ %1 ], 16;"
                 :: "r"(smem_u32(s)), "l"(g));
}
__device__ __forceinline__ void cp_commit() {
    asm volatile("cp.async.commit_group;");
}
template <int N>
__device__ __forceinline__ void cp_wait() {
    asm volatile("cp.async.wait_group %0;" :: "n"(N));
}

// ---------------- data prep: fp32 -> fp16 ----------------------------------
template <int SEL>
__global__ void convert_kernel(const float* __restrict__ src) {
    __half* dst = (SEL == 0) ? g_wqkvB : (SEL == 1) ? g_wfcB : g_x;
    size_t i = ((size_t)blockIdx.x * blockDim.x + threadIdx.x) * 8;
    float4 f0 = *(const float4*)(src + i);
    float4 f1 = *(const float4*)(src + i + 4);
    __half2 h[4];
    h[0] = __floats2half2_rn(f0.x, f0.y);
    h[1] = __floats2half2_rn(f0.z, f0.w);
    h[2] = __floats2half2_rn(f1.x, f1.y);
    h[3] = __floats2half2_rn(f1.z, f1.w);
    *(uint4*)(dst + i) = *(uint4*)h;
}

// ---------------- HGEMM: R6 engine (32-K chunks) with K=1024 ---------------
#define GSTG 3
#define SA_ST (128 * 40)
#define SB_ST (32 * 136)
#define HGEMM_SMEM ((GSTG * (SA_ST + SB_ST)) * 2)   // 56832 B

template <int EPI>
__global__ __launch_bounds__(128, 2) void hgemm_kernel(
    const float* __restrict__ bias, float* __restrict__ C, int N)
{
    extern __shared__ __half hsm[];
    __half* sAbase = hsm;
    __half* sBbase = hsm + GSTG * SA_ST;

    const __half* __restrict__ A = (EPI == 0) ? g_x : g_ctx;
    const __half* __restrict__ B = (EPI == 0) ? g_wqkvB : g_wfcB;

    const int tid = threadIdx.x;
    const int wid = tid >> 5, lane = tid & 31;
    const int wm = (wid & 1) * 64;
    const int wn = (wid >> 1) * 64;
    const int m0 = blockIdx.y * 128;
    const int n0 = blockIdx.x * 128;

    float acc[4][8][4];
#pragma unroll
    for (int mt = 0; mt < 4; mt++)
#pragma unroll
        for (int nt = 0; nt < 8; nt++)
#pragma unroll
            for (int r = 0; r < 4; r++) acc[mt][nt][r] = 0.f;

    // loaders (128 threads): A 128x32 (4 passes of 32 rows), B 32x128 (4 passes of 8 rows)
    const int ar0 = tid >> 2, ac0 = (tid & 3) * 8;
    const int br0 = tid >> 4, bc0 = (tid & 15) * 8;

#define LOAD_TILE(t, stg) do {                                                    \
        const int k0_ = (t) * 32;                                                \
        __half* sA_ = sAbase + (stg) * SA_ST;                                    \
        __half* sB_ = sBbase + (stg) * SB_ST;                                    \
        _Pragma("unroll")                                                         \
        for (int i_ = 0; i_ < 4; i_++) {                                         \
            const int r_ = ar0 + i_ * 32;                                        \
            cpa16(sA_ + r_ * 40 + ac0, A + (size_t)(m0 + r_) * EMB + k0_ + ac0); \
        }                                                                         \
        _Pragma("unroll")                                                         \
        for (int i_ = 0; i_ < 4; i_++) {                                         \
            const int r_ = br0 + i_ * 8;                                         \
            cpa16(sB_ + r_ * 136 + bc0,                                          \
                  B + (size_t)(k0_ + r_) * N + n0 + bc0);                        \
        }                                                                         \
        cp_commit();                                                             \
    } while (0)

    const int T = EMB / 32;    // 32
    LOAD_TILE(0, 0);
    LOAD_TILE(1, 1);

    int stg = 0;
    for (int t = 0; t < T; t++) {
        if (t < T - 1) cp_wait<1>(); else cp_wait<0>();
        __syncthreads();
        if (t + 2 < T) {
            int ns = stg + 2; if (ns >= GSTG) ns -= GSTG;
            LOAD_TILE(t + 2, ns);
        }
        __half* sA_ = sAbase + stg * SA_ST;
        __half* sB_ = sBbase + stg * SB_ST;
#pragma unroll
        for (int ks = 0; ks < 2; ks++) {
            uint32_t a[4][4];
#pragma unroll
            for (int mt = 0; mt < 4; mt++)
                ldm_x4(a[mt][0], a[mt][1], a[mt][2], a[mt][3],
                       smem_u32(sA_ + (wm + mt * 16 + (lane & 15)) * 40 + ks * 16 + (lane >> 4) * 8));
            uint32_t b[16];
#pragma unroll
            for (int nn = 0; nn < 4; nn++)
                ldm_x4_t(b[nn * 4 + 0], b[nn * 4 + 1], b[nn * 4 + 2], b[nn * 4 + 3],
                         smem_u32(sB_ + (ks * 16 + (lane & 15)) * 136 + wn + nn * 16 + (lane >> 4) * 8));
#pragma unroll
            for (int mt = 0; mt < 4; mt++)
#pragma unroll
                for (int nt = 0; nt < 8; nt++)
                    mma16816(acc[mt][nt], a[mt][0], a[mt][1], a[mt][2], a[mt][3],
                             b[nt * 2], b[nt * 2 + 1]);
        }
        stg++; if (stg >= GSTG) stg = 0;
    }
#undef LOAD_TILE

#pragma unroll
    for (int mt = 0; mt < 4; mt++) {
#pragma unroll
        for (int nt = 0; nt < 8; nt++) {
#pragma unroll
            for (int ri = 0; ri < 2; ri++) {
                const int m = m0 + wm + mt * 16 + (lane >> 2) + ri * 8;
                const int n = n0 + wn + nt * 8 + 2 * (lane & 3);
                float f0 = acc[mt][nt][ri * 2 + 0] + bias[n];
                float f1 = acc[mt][nt][ri * 2 + 1] + bias[n + 1];
                if (EPI == 1) {
                    float2 o;
                    o.x = f0;
                    o.y = f1;
                    *(float2*)(C + (size_t)m * N + n) = o;
                } else {
                    // natural-layout coalesced QKV stores
                    const int wh = n >> 10;     // 0=q 1=k 2=v
                    const int e  = n & 1023;
                    if (wh == 0) {
                        f0 *= 0.125f; f1 *= 0.125f;
                        __half h0 = __float2half_rn(f0);
                        __half h1 = __float2half_rn(f1);
                        __half l0 = __float2half_rn(f0 - __half2float(h0));
                        __half l1 = __float2half_rn(f1 - __half2float(h1));
                        __half* p = g_qn + (size_t)m * 2048 + e;
                        *(__half2*)p          = __halves2half2(h0, h1);
                        *(__half2*)(p + 1024) = __halves2half2(l0, l1);
                    } else if (wh == 1) {
                        *(__half2*)(g_kn + (size_t)m * EMB + e) = __floats2half2_rn(f0, f1);
                    } else {
                        *(__half2*)(g_vn + (size_t)m * EMB + e) = __floats2half2_rn(f0, f1);
                    }
                }
            }
        }
    }
}

// ---------------- flash attention: S=(qh+ql)kh, 2-stage cp.async -----------
#define SQ_STRIDE 136
#define SK_STRIDE 72
#define SV_STRIDE 72
#define FLASH_SMEM ((64 * SQ_STRIDE + 2 * 64 * SK_STRIDE + 2 * 64 * SV_STRIDE) * 2)  // 54272 B

__global__ __launch_bounds__(128) void flash_kernel()
{
    extern __shared__ __half fsm[];
    __half* sQ  = fsm;
    __half* sK0 = fsm + 64 * SQ_STRIDE;
    __half* sV0 = sK0 + 2 * 64 * SK_STRIDE;

    const int tid = threadIdx.x, wid = tid >> 5, lane = tid & 31;
    const int qt = blockIdx.x, hh = blockIdx.y, bz = blockIdx.z;

    const size_t mbase = (size_t)bz * SEQ;
    const __half* Qg = g_qn + (mbase + (size_t)qt * 64) * 2048 + hh * 64;   // qh; ql at +1024
    const __half* Kg = g_kn + mbase * EMB + hh * 64;                        // row stride EMB
    const __half* Vg = g_vn + mbase * EMB + hh * 64;

#define LOAD_KV(kt, stg) do {                                               \
        const __half* Kt_ = Kg + (size_t)(kt) * 64 * EMB;                  \
        const __half* Vt_ = Vg + (size_t)(kt) * 64 * EMB;                  \
        __half* sK_ = sK0 + (stg) * 64 * SK_STRIDE;                        \
        __half* sV_ = sV0 + (stg) * 64 * SV_STRIDE;                        \
        _Pragma("unroll")                                                   \
        for (int i_ = 0; i_ < 4; i_++) {                                   \
            int u_ = tid + i_ * 128;                                       \
            int r_ = u_ >> 3, c_ = (u_ & 7) * 8;                           \
            cpa16(sK_ + r_ * SK_STRIDE + c_, Kt_ + (size_t)r_ * EMB + c_); \
            cpa16(sV_ + r_ * SV_STRIDE + c_, Vt_ + (size_t)r_ * EMB + c_); \
        }                                                                   \
        cp_commit();                                                       \
    } while (0)

    // Q tile: cols 0..63 = qh, 64..127 = ql
#pragma unroll
    for (int i = 0; i < 8; i++) {
        int u = tid + i * 128;
        int row = u >> 4, seg = u & 15;
        const __half* src = (seg < 8)
            ? (Qg + (size_t)row * 2048 + seg * 8)
            : (Qg + (size_t)row * 2048 + 1024 + (seg - 8) * 8);
        *(uint4*)(sQ + row * SQ_STRIDE + seg * 8) = *(const uint4*)src;
    }
    LOAD_KV(0, 0);
    __syncthreads();

    uint32_t qf[8][4];
#pragma unroll
    for (int ks = 0; ks < 8; ks++)
        ldm_x4(qf[ks][0], qf[ks][1], qf[ks][2], qf[ks][3],
               smem_u32(sQ + (wid * 16 + (lane & 15)) * SQ_STRIDE + ks * 16 + (lane >> 4) * 8));

    float O[8][4];
#pragma unroll
    for (int dt = 0; dt < 8; dt++)
#pragma unroll
        for (int r = 0; r < 4; r++) O[dt][r] = 0.f;
    float mrow[2];
    float lrow[2];
    mrow[0] = -1e30f; mrow[1] = -1e30f;
    lrow[0] = 0.f;    lrow[1] = 0.f;

    const int qrow0 = wid * 16 + (lane >> 2);

    for (int kt = 0; kt <= qt; kt++) {
        cp_wait<0>();
        __syncthreads();
        if (kt < qt) LOAD_KV(kt + 1, (kt + 1) & 1);

        const __half* sK_ = sK0 + (kt & 1) * 64 * SK_STRIDE;
        const __half* sV_ = sV0 + (kt & 1) * 64 * SV_STRIDE;

        float S[8][4];
#pragma unroll
        for (int nt = 0; nt < 8; nt++)
#pragma unroll
            for (int r = 0; r < 4; r++) S[nt][r] = 0.f;

        const int klr = (lane >> 4) * 8 + (lane & 7);
        const int klc = ((lane >> 3) & 1) * 8;
#pragma unroll
        for (int ks = 0; ks < 8; ks++) {
#pragma unroll
            for (int jp = 0; jp < 4; jp++) {
                uint32_t b0, b1, b2, b3;
                ldm_x4(b0, b1, b2, b3,
                       smem_u32(sK_ + (jp * 16 + klr) * SK_STRIDE + (ks & 3) * 16 + klc));
                mma16816(S[jp * 2 + 0], qf[ks][0], qf[ks][1], qf[ks][2], qf[ks][3], b0, b1);
                mma16816(S[jp * 2 + 1], qf[ks][0], qf[ks][1], qf[ks][2], qf[ks][3], b2, b3);
            }
        }

        if (kt == qt) {
#pragma unroll
            for (int nt = 0; nt < 8; nt++) {
                const int jc = nt * 8 + 2 * (lane & 3);
#pragma unroll
                for (int ri = 0; ri < 2; ri++) {
                    const int ii = qrow0 + ri * 8;
                    if (jc     > ii) S[nt][ri * 2 + 0] = -1e30f;
                    if (jc + 1 > ii) S[nt][ri * 2 + 1] = -1e30f;
                }
            }
        }

#pragma unroll
        for (int ri = 0; ri < 2; ri++) {
            float tmax = -1e30f;
#pragma unroll
            for (int nt = 0; nt < 8; nt++)
                tmax = fmaxf(tmax, fmaxf(S[nt][ri * 2], S[nt][ri * 2 + 1]));
            tmax = fmaxf(tmax, __shfl_xor_sync(0xffffffffu, tmax, 1));
            tmax = fmaxf(tmax, __shfl_xor_sync(0xffffffffu, tmax, 2));
            const float mnew = fmaxf(mrow[ri], tmax);
            const float scale = __expf(mrow[ri] - mnew);
            float rs = 0.f;
#pragma unroll
            for (int nt = 0; nt < 8; nt++) {
                float p0 = __expf(S[nt][ri * 2 + 0] - mnew);
                float p1 = __expf(S[nt][ri * 2 + 1] - mnew);
                S[nt][ri * 2 + 0] = p0;
                S[nt][ri * 2 + 1] = p1;
                rs += p0 + p1;
            }
            rs += __shfl_xor_sync(0xffffffffu, rs, 1);
            rs += __shfl_xor_sync(0xffffffffu, rs, 2);
            lrow[ri] = lrow[ri] * scale + rs;
            mrow[ri] = mnew;
#pragma unroll
            for (int dt = 0; dt < 8; dt++) {
                O[dt][ri * 2 + 0] *= scale;
                O[dt][ri * 2 + 1] *= scale;
            }
        }

        const int vrow = lane & 15;
        const int vcol = (lane >> 4) * 8;
#pragma unroll
        for (int kk = 0; kk < 4; kk++) {
            uint32_t a0 = packh2(S[kk * 2 + 0][0], S[kk * 2 + 0][1]);
            uint32_t a1 = packh2(S[kk * 2 + 0][2], S[kk * 2 + 0][3]);
            uint32_t a2 = packh2(S[kk * 2 + 1][0], S[kk * 2 + 1][1]);
            uint32_t a3 = packh2(S[kk * 2 + 1][2], S[kk * 2 + 1][3]);
#pragma unroll
            for (int dp = 0; dp < 4; dp++) {
                uint32_t b0, b1, b2, b3;
                ldm_x4_t(b0, b1, b2, b3,
                         smem_u32(sV_ + (kk * 16 + vrow) * SV_STRIDE + dp * 16 + vcol));
                mma16816(O[dp * 2 + 0], a0, a1, a2, a3, b0, b1);
                mma16816(O[dp * 2 + 1], a0, a1, a2, a3, b2, b3);
            }
        }
    }
#undef LOAD_KV

    // ---- normalize + write ctx fp16 [B*S, EMB] ----
#pragma unroll
    for (int ri = 0; ri < 2; ri++) {
        const float inv = 1.f / lrow[ri];
        const size_t mg = mbase + (size_t)qt * 64 + qrow0 + ri * 8;
#pragma unroll
        for (int dt = 0; dt < 8; dt++) {
            const int col = hh * 64 + dt * 8 + 2 * (lane & 3);
            __half2 hv = __floats2half2_rn(O[dt][ri * 2 + 0] * inv, O[dt][ri * 2 + 1] * inv);
            *(__half2*)(g_ctx + mg * EMB + col) = hv;
        }
    }
}

// ---------------------------------------------------------------------------
extern "C" void kernel_launch(void* const* d_in, const int* in_sizes, int n_in,
                              void* d_out, int out_size)
{
    const float* x     = (const float*)d_in[0];
    const float* w_qkv = (const float*)d_in[1];
    const float* b_qkv = (const float*)d_in[2];
    const float* w_fc  = (const float*)d_in[3];
    const float* b_fc  = (const float*)d_in[4];
    float* out = (float*)d_out;

    static int attr_done = 0;
    if (!attr_done) {
        cudaFuncSetAttribute(hgemm_kernel<0>, cudaFuncAttributeMaxDynamicSharedMemorySize, HGEMM_SMEM);
        cudaFuncSetAttribute(hgemm_kernel<1>, cudaFuncAttributeMaxDynamicSharedMemorySize, HGEMM_SMEM);
        cudaFuncSetAttribute(flash_kernel, cudaFuncAttributeMaxDynamicSharedMemorySize, FLASH_SMEM);
        attr_done = 1;
    }

    convert_kernel<2><<<MROWS * EMB / 8 / 256, 256>>>(x);
    convert_kernel<0><<<EMB * 3 * EMB / 8 / 256, 256>>>(w_qkv);
    convert_kernel<1><<<EMB * EMB / 8 / 256, 256>>>(w_fc);

    // 1) QKV projection (R6 engine, K=1024, coalesced stores)
    hgemm_kernel<0><<<dim3(24, 64), 128, HGEMM_SMEM>>>(b_qkv, nullptr, 3 * EMB);

    // 2) causal flash attention
    flash_kernel<<<dim3(SEQ / 64, HEADS, BATCH), 128, FLASH_SMEM>>>();

    // 3) output projection
    hgemm_kernel<1><<<dim3(8, 64), 128, HGEMM_SMEM>>>(b_fc, out, EMB);
}

// round 11
// speedup vs baseline: 8.4938x; 1.1044x over previous
#include <cuda_runtime.h>
#include <cuda_fp16.h>
#include <math.h>
#include <stdint.h>

#define EMB 1024
#define HEADS 16
#define DH 64
#define BATCH 4
#define SEQ 2048
#define MROWS (BATCH * SEQ)   // 8192

// ---------------- scratch (device globals; no runtime allocation) ----------
__device__ __half g_x    [(size_t)MROWS * EMB];       // x fp16
__device__ __half g_wqkvB[(size_t)EMB * (3 * EMB)];   // [k][n] fp16
__device__ __half g_wfcB [(size_t)EMB * EMB];         // [k][n] fp16
__device__ __half g_qn   [(size_t)MROWS * EMB];       // q fp16, pre-scaled 1/8
__device__ __half g_kn   [(size_t)MROWS * EMB];       // [m][h*64+d]
__device__ __half g_vn   [(size_t)MROWS * EMB];
__device__ __half g_ctx  [(size_t)MROWS * EMB];       // attention out fp16

// ---------------- helpers --------------------------------------------------
__device__ __forceinline__ uint32_t smem_u32(const void* p) {
    return (uint32_t)__cvta_generic_to_shared(p);
}
__device__ __forceinline__ void ldm_x4(uint32_t& r0, uint32_t& r1, uint32_t& r2, uint32_t& r3, uint32_t addr) {
    asm volatile("ldmatrix.sync.aligned.m8n8.x4.shared.b16 { %0, %1, %2, %3 }, [ %4 ];"
                 : "=r"(r0), "=r"(r1), "=r"(r2), "=r"(r3) : "r"(addr));
}
__device__ __forceinline__ void ldm_x4_t(uint32_t& r0, uint32_t& r1, uint32_t& r2, uint32_t& r3, uint32_t addr) {
    asm volatile("ldmatrix.sync.aligned.m8n8.x4.trans.shared.b16 { %0, %1, %2, %3 }, [ %4 ];"
                 : "=r"(r0), "=r"(r1), "=r"(r2), "=r"(r3) : "r"(addr));
}
__device__ __forceinline__ void mma16816(float* c, uint32_t a0, uint32_t a1, uint32_t a2, uint32_t a3,
                                         uint32_t b0, uint32_t b1) {
    asm volatile("mma.sync.aligned.m16n8k16.row.col.f32.f16.f16.f32 "
                 "{ %0, %1, %2, %3 }, { %4, %5, %6, %7 }, { %8, %9 }, { %0, %1, %2, %3 };"
                 : "+f"(c[0]), "+f"(c[1]), "+f"(c[2]), "+f"(c[3])
                 : "r"(a0), "r"(a1), "r"(a2), "r"(a3), "r"(b0), "r"(b1));
}
__device__ __forceinline__ uint32_t packh2(float a, float b) {
    __half2 h = __floats2half2_rn(a, b);
    return *(uint32_t*)&h;
}
__device__ __forceinline__ void cpa16(void* s, const void* g) {
    asm volatile("cp.async.cg.shared.global [ %0 ], [ %1 ], 16;"
                 :: "r"(smem_u32(s)), "l"(g));
}
__device__ __forceinline__ void cp_commit() {
    asm volatile("cp.async.commit_group;");
}
template <int N>
__device__ __forceinline__ void cp_wait() {
    asm volatile("cp.async.wait_group %0;" :: "n"(N));
}

// ---------------- data prep: fp32 -> fp16 ----------------------------------
template <int SEL>
__global__ void convert_kernel(const float* __restrict__ src) {
    __half* dst = (SEL == 0) ? g_wqkvB : (SEL == 1) ? g_wfcB : g_x;
    size_t i = ((size_t)blockIdx.x * blockDim.x + threadIdx.x) * 8;
    float4 f0 = *(const float4*)(src + i);
    float4 f1 = *(const float4*)(src + i + 4);
    __half2 h[4];
    h[0] = __floats2half2_rn(f0.x, f0.y);
    h[1] = __floats2half2_rn(f0.z, f0.w);
    h[2] = __floats2half2_rn(f1.x, f1.y);
    h[3] = __floats2half2_rn(f1.z, f1.w);
    *(uint4*)(dst + i) = *(uint4*)h;
}

// ---------------- HGEMM: R6 engine (32-K chunks), K=1024 -------------------
#define GSTG 3
#define SA_ST (128 * 40)
#define SB_ST (32 * 136)
#define HGEMM_SMEM ((GSTG * (SA_ST + SB_ST)) * 2)   // 56832 B

template <int EPI>
__global__ __launch_bounds__(128, 2) void hgemm_kernel(
    const float* __restrict__ bias, float* __restrict__ C, int N)
{
    extern __shared__ __half hsm[];
    __half* sAbase = hsm;
    __half* sBbase = hsm + GSTG * SA_ST;

    const __half* __restrict__ A = (EPI == 0) ? g_x : g_ctx;
    const __half* __restrict__ B = (EPI == 0) ? g_wqkvB : g_wfcB;

    const int tid = threadIdx.x;
    const int wid = tid >> 5, lane = tid & 31;
    const int wm = (wid & 1) * 64;
    const int wn = (wid >> 1) * 64;
    const int m0 = blockIdx.y * 128;
    const int n0 = blockIdx.x * 128;

    float acc[4][8][4];
#pragma unroll
    for (int mt = 0; mt < 4; mt++)
#pragma unroll
        for (int nt = 0; nt < 8; nt++)
#pragma unroll
            for (int r = 0; r < 4; r++) acc[mt][nt][r] = 0.f;

    const int ar0 = tid >> 2, ac0 = (tid & 3) * 8;
    const int br0 = tid >> 4, bc0 = (tid & 15) * 8;

#define LOAD_TILE(t, stg) do {                                                    \
        const int k0_ = (t) * 32;                                                \
        __half* sA_ = sAbase + (stg) * SA_ST;                                    \
        __half* sB_ = sBbase + (stg) * SB_ST;                                    \
        _Pragma("unroll")                                                         \
        for (int i_ = 0; i_ < 4; i_++) {                                         \
            const int r_ = ar0 + i_ * 32;                                        \
            cpa16(sA_ + r_ * 40 + ac0, A + (size_t)(m0 + r_) * EMB + k0_ + ac0); \
        }                                                                         \
        _Pragma("unroll")                                                         \
        for (int i_ = 0; i_ < 4; i_++) {                                         \
            const int r_ = br0 + i_ * 8;                                         \
            cpa16(sB_ + r_ * 136 + bc0,                                          \
                  B + (size_t)(k0_ + r_) * N + n0 + bc0);                        \
        }                                                                         \
        cp_commit();                                                             \
    } while (0)

    const int T = EMB / 32;    // 32
    LOAD_TILE(0, 0);
    LOAD_TILE(1, 1);

    int stg = 0;
    for (int t = 0; t < T; t++) {
        if (t < T - 1) cp_wait<1>(); else cp_wait<0>();
        __syncthreads();
        if (t + 2 < T) {
            int ns = stg + 2; if (ns >= GSTG) ns -= GSTG;
            LOAD_TILE(t + 2, ns);
        }
        __half* sA_ = sAbase + stg * SA_ST;
        __half* sB_ = sBbase + stg * SB_ST;
#pragma unroll
        for (int ks = 0; ks < 2; ks++) {
            uint32_t a[4][4];
#pragma unroll
            for (int mt = 0; mt < 4; mt++)
                ldm_x4(a[mt][0], a[mt][1], a[mt][2], a[mt][3],
                       smem_u32(sA_ + (wm + mt * 16 + (lane & 15)) * 40 + ks * 16 + (lane >> 4) * 8));
            uint32_t b[16];
#pragma unroll
            for (int nn = 0; nn < 4; nn++)
                ldm_x4_t(b[nn * 4 + 0], b[nn * 4 + 1], b[nn * 4 + 2], b[nn * 4 + 3],
                         smem_u32(sB_ + (ks * 16 + (lane & 15)) * 136 + wn + nn * 16 + (lane >> 4) * 8));
#pragma unroll
            for (int mt = 0; mt < 4; mt++)
#pragma unroll
                for (int nt = 0; nt < 8; nt++)
                    mma16816(acc[mt][nt], a[mt][0], a[mt][1], a[mt][2], a[mt][3],
                             b[nt * 2], b[nt * 2 + 1]);
        }
        stg++; if (stg >= GSTG) stg = 0;
    }
#undef LOAD_TILE

#pragma unroll
    for (int mt = 0; mt < 4; mt++) {
#pragma unroll
        for (int nt = 0; nt < 8; nt++) {
#pragma unroll
            for (int ri = 0; ri < 2; ri++) {
                const int m = m0 + wm + mt * 16 + (lane >> 2) + ri * 8;
                const int n = n0 + wn + nt * 8 + 2 * (lane & 3);
                float f0 = acc[mt][nt][ri * 2 + 0] + bias[n];
                float f1 = acc[mt][nt][ri * 2 + 1] + bias[n + 1];
                if (EPI == 1) {
                    float2 o;
                    o.x = f0;
                    o.y = f1;
                    *(float2*)(C + (size_t)m * N + n) = o;
                } else {
                    const int wh = n >> 10;     // 0=q 1=k 2=v
                    const int e  = n & 1023;
                    if (wh == 0) {
                        *(__half2*)(g_qn + (size_t)m * EMB + e) =
                            __floats2half2_rn(f0 * 0.125f, f1 * 0.125f);
                    } else if (wh == 1) {
                        *(__half2*)(g_kn + (size_t)m * EMB + e) = __floats2half2_rn(f0, f1);
                    } else {
                        *(__half2*)(g_vn + (size_t)m * EMB + e) = __floats2half2_rn(f0, f1);
                    }
                }
            }
        }
    }
}

// ---------------- flash attention: plain-fp16 scores, 2-stage cp.async -----
#define SQ_STRIDE 72
#define SK_STRIDE 72
#define SV_STRIDE 72
#define FLASH_SMEM ((64 * SQ_STRIDE + 2 * 64 * SK_STRIDE + 2 * 64 * SV_STRIDE) * 2)  // 46080 B

__global__ __launch_bounds__(128) void flash_kernel()
{
    extern __shared__ __half fsm[];
    __half* sQ  = fsm;
    __half* sK0 = fsm + 64 * SQ_STRIDE;
    __half* sV0 = sK0 + 2 * 64 * SK_STRIDE;

    const int tid = threadIdx.x, wid = tid >> 5, lane = tid & 31;
    const int qt = blockIdx.x, hh = blockIdx.y, bz = blockIdx.z;

    const size_t mbase = (size_t)bz * SEQ;
    const __half* Qg = g_qn + (mbase + (size_t)qt * 64) * EMB + hh * 64;   // row stride EMB
    const __half* Kg = g_kn + mbase * EMB + hh * 64;
    const __half* Vg = g_vn + mbase * EMB + hh * 64;

#define LOAD_KV(kt, stg) do {                                               \
        const __half* Kt_ = Kg + (size_t)(kt) * 64 * EMB;                  \
        const __half* Vt_ = Vg + (size_t)(kt) * 64 * EMB;                  \
        __half* sK_ = sK0 + (stg) * 64 * SK_STRIDE;                        \
        __half* sV_ = sV0 + (stg) * 64 * SV_STRIDE;                        \
        _Pragma("unroll")                                                   \
        for (int i_ = 0; i_ < 4; i_++) {                                   \
            int u_ = tid + i_ * 128;                                       \
            int r_ = u_ >> 3, c_ = (u_ & 7) * 8;                           \
            cpa16(sK_ + r_ * SK_STRIDE + c_, Kt_ + (size_t)r_ * EMB + c_); \
            cpa16(sV_ + r_ * SV_STRIDE + c_, Vt_ + (size_t)r_ * EMB + c_); \
        }                                                                   \
        cp_commit();                                                       \
    } while (0)

    // Q tile: 64 x 64
#pragma unroll
    for (int i = 0; i < 4; i++) {
        int u = tid + i * 128;
        int row = u >> 3, c = (u & 7) * 8;
        *(uint4*)(sQ + row * SQ_STRIDE + c) = *(const uint4*)(Qg + (size_t)row * EMB + c);
    }
    LOAD_KV(0, 0);
    __syncthreads();

    uint32_t qf[4][4];
#pragma unroll
    for (int ks = 0; ks < 4; ks++)
        ldm_x4(qf[ks][0], qf[ks][1], qf[ks][2], qf[ks][3],
               smem_u32(sQ + (wid * 16 + (lane & 15)) * SQ_STRIDE + ks * 16 + (lane >> 4) * 8));

    float O[8][4];
#pragma unroll
    for (int dt = 0; dt < 8; dt++)
#pragma unroll
        for (int r = 0; r < 4; r++) O[dt][r] = 0.f;
    float mrow[2];
    float lrow[2];
    mrow[0] = -1e30f; mrow[1] = -1e30f;
    lrow[0] = 0.f;    lrow[1] = 0.f;

    const int qrow0 = wid * 16 + (lane >> 2);

    for (int kt = 0; kt <= qt; kt++) {
        cp_wait<0>();
        __syncthreads();
        if (kt < qt) LOAD_KV(kt + 1, (kt + 1) & 1);

        const __half* sK_ = sK0 + (kt & 1) * 64 * SK_STRIDE;
        const __half* sV_ = sV0 + (kt & 1) * 64 * SV_STRIDE;

        float S[8][4];
#pragma unroll
        for (int nt = 0; nt < 8; nt++)
#pragma unroll
            for (int r = 0; r < 4; r++) S[nt][r] = 0.f;

        const int klr = (lane >> 4) * 8 + (lane & 7);
        const int klc = ((lane >> 3) & 1) * 8;
#pragma unroll
        for (int ks = 0; ks < 4; ks++) {
#pragma unroll
            for (int jp = 0; jp < 4; jp++) {
                uint32_t b0, b1, b2, b3;
                ldm_x4(b0, b1, b2, b3,
                       smem_u32(sK_ + (jp * 16 + klr) * SK_STRIDE + ks * 16 + klc));
                mma16816(S[jp * 2 + 0], qf[ks][0], qf[ks][1], qf[ks][2], qf[ks][3], b0, b1);
                mma16816(S[jp * 2 + 1], qf[ks][0], qf[ks][1], qf[ks][2], qf[ks][3], b2, b3);
            }
        }

        if (kt == qt) {
#pragma unroll
            for (int nt = 0; nt < 8; nt++) {
                const int jc = nt * 8 + 2 * (lane & 3);
#pragma unroll
                for (int ri = 0; ri < 2; ri++) {
                    const int ii = qrow0 + ri * 8;
                    if (jc     > ii) S[nt][ri * 2 + 0] = -1e30f;
                    if (jc + 1 > ii) S[nt][ri * 2 + 1] = -1e30f;
                }
            }
        }

#pragma unroll
        for (int ri = 0; ri < 2; ri++) {
            float tmax = -1e30f;
#pragma unroll
            for (int nt = 0; nt < 8; nt++)
                tmax = fmaxf(tmax, fmaxf(S[nt][ri * 2], S[nt][ri * 2 + 1]));
            tmax = fmaxf(tmax, __shfl_xor_sync(0xffffffffu, tmax, 1));
            tmax = fmaxf(tmax, __shfl_xor_sync(0xffffffffu, tmax, 2));
            const float mnew = fmaxf(mrow[ri], tmax);
            const float scale = __expf(mrow[ri] - mnew);
            float rs = 0.f;
#pragma unroll
            for (int nt = 0; nt < 8; nt++) {
                float p0 = __expf(S[nt][ri * 2 + 0] - mnew);
                float p1 = __expf(S[nt][ri * 2 + 1] - mnew);
                S[nt][ri * 2 + 0] = p0;
                S[nt][ri * 2 + 1] = p1;
                rs += p0 + p1;
            }
            rs += __shfl_xor_sync(0xffffffffu, rs, 1);
            rs += __shfl_xor_sync(0xffffffffu, rs, 2);
            lrow[ri] = lrow[ri] * scale + rs;
            mrow[ri] = mnew;
#pragma unroll
            for (int dt = 0; dt < 8; dt++) {
                O[dt][ri * 2 + 0] *= scale;
                O[dt][ri * 2 + 1] *= scale;
            }
        }

        const int vrow = lane & 15;
        const int vcol = (lane >> 4) * 8;
#pragma unroll
        for (int kk = 0; kk < 4; kk++) {
            uint32_t a0 = packh2(S[kk * 2 + 0][0], S[kk * 2 + 0][1]);
            uint32_t a1 = packh2(S[kk * 2 + 0][2], S[kk * 2 + 0][3]);
            uint32_t a2 = packh2(S[kk * 2 + 1][0], S[kk * 2 + 1][1]);
            uint32_t a3 = packh2(S[kk * 2 + 1][2], S[kk * 2 + 1][3]);
#pragma unroll
            for (int dp = 0; dp < 4; dp++) {
                uint32_t b0, b1, b2, b3;
                ldm_x4_t(b0, b1, b2, b3,
                         smem_u32(sV_ + (kk * 16 + vrow) * SV_STRIDE + dp * 16 + vcol));
                mma16816(O[dp * 2 + 0], a0, a1, a2, a3, b0, b1);
                mma16816(O[dp * 2 + 1], a0, a1, a2, a3, b2, b3);
            }
        }
    }
#undef LOAD_KV

    // ---- normalize + write ctx fp16 [B*S, EMB] ----
#pragma unroll
    for (int ri = 0; ri < 2; ri++) {
        const float inv = 1.f / lrow[ri];
        const size_t mg = mbase + (size_t)qt * 64 + qrow0 + ri * 8;
#pragma unroll
        for (int dt = 0; dt < 8; dt++) {
            const int col = hh * 64 + dt * 8 + 2 * (lane & 3);
            __half2 hv = __floats2half2_rn(O[dt][ri * 2 + 0] * inv, O[dt][ri * 2 + 1] * inv);
            *(__half2*)(g_ctx + mg * EMB + col) = hv;
        }
    }
}

// ---------------------------------------------------------------------------
extern "C" void kernel_launch(void* const* d_in, const int* in_sizes, int n_in,
                              void* d_out, int out_size)
{
    const float* x     = (const float*)d_in[0];
    const float* w_qkv = (const float*)d_in[1];
    const float* b_qkv = (const float*)d_in[2];
    const float* w_fc  = (const float*)d_in[3];
    const float* b_fc  = (const float*)d_in[4];
    float* out = (float*)d_out;

    static int attr_done = 0;
    if (!attr_done) {
        cudaFuncSetAttribute(hgemm_kernel<0>, cudaFuncAttributeMaxDynamicSharedMemorySize, HGEMM_SMEM);
        cudaFuncSetAttribute(hgemm_kernel<1>, cudaFuncAttributeMaxDynamicSharedMemorySize, HGEMM_SMEM);
        cudaFuncSetAttribute(flash_kernel, cudaFuncAttributeMaxDynamicSharedMemorySize, FLASH_SMEM);
        attr_done = 1;
    }

    convert_kernel<2><<<MROWS * EMB / 8 / 256, 256>>>(x);
    convert_kernel<0><<<EMB * 3 * EMB / 8 / 256, 256>>>(w_qkv);
    convert_kernel<1><<<EMB * EMB / 8 / 256, 256>>>(w_fc);

    // 1) QKV projection
    hgemm_kernel<0><<<dim3(24, 64), 128, HGEMM_SMEM>>>(b_qkv, nullptr, 3 * EMB);

    // 2) causal flash attention (plain fp16 scores)
    flash_kernel<<<dim3(SEQ / 64, HEADS, BATCH), 128, FLASH_SMEM>>>();

    // 3) output projection
    hgemm_kernel<1><<<dim3(8, 64), 128, HGEMM_SMEM>>>(b_fc, out, EMB);
}